// round 5
// baseline (speedup 1.0000x reference)
#include <cuda_runtime.h>
#include <cuda_bf16.h>
#include <cstdint>

#define BB    16
#define CIN   512
#define COUT  512
#define RES   64
#define WDIM  512
#define PADW  66
#define NPIX  (PADW * PADW)

// ---------------------------------------------------------------------------
// device scratch (static globals — no allocations allowed)
// ---------------------------------------------------------------------------
__device__ float g_styles[BB * CIN];
__device__ float g_wsqT[CIN * COUT];
__device__ float g_dcoefs[BB * COUT];
// packed weights: [tap][cout][cin], bf16 hi/lo planes
__device__ __align__(1024) __nv_bfloat16 g_ah[9ull * COUT * CIN];
__device__ __align__(1024) __nv_bfloat16 g_al[9ull * COUT * CIN];
// packed modulated input: [b][padded pixel][cin], bf16 hi/lo planes
__device__ __align__(1024) __nv_bfloat16 g_xh[(size_t)BB * NPIX * CIN];
__device__ __align__(1024) __nv_bfloat16 g_xl[(size_t)BB * NPIX * CIN];

// ---------------------------------------------------------------------------
// PTX helpers (baseline compute_103-safe: no tcgen05)
// ---------------------------------------------------------------------------
__device__ __forceinline__ uint32_t smem_u32(const void* p) {
    uint32_t a;
    asm("{ .reg .u64 t; cvta.to.shared.u64 t, %1; cvt.u32.u64 %0, t; }" : "=r"(a) : "l"(p));
    return a;
}
__device__ __forceinline__ void cpa16(uint32_t dst, const void* src) {
    asm volatile("cp.async.cg.shared.global [%0], [%1], 16;" :: "r"(dst), "l"(src));
}
#define CP_COMMIT()  asm volatile("cp.async.commit_group;" ::: "memory")
#define CP_WAIT1()   asm volatile("cp.async.wait_group 1;" ::: "memory")
#define CP_WAIT0()   asm volatile("cp.async.wait_group 0;" ::: "memory")

__device__ __forceinline__ void ldsm4(uint32_t* r, uint32_t a) {
    asm volatile("ldmatrix.sync.aligned.m8n8.x4.shared.b16 {%0,%1,%2,%3}, [%4];"
        : "=r"(r[0]), "=r"(r[1]), "=r"(r[2]), "=r"(r[3]) : "r"(a));
}
__device__ __forceinline__ void ldsm2(uint32_t* r, uint32_t a) {
    asm volatile("ldmatrix.sync.aligned.m8n8.x2.shared.b16 {%0,%1}, [%2];"
        : "=r"(r[0]), "=r"(r[1]) : "r"(a));
}
__device__ __forceinline__ void mma_bf16(float* c, const uint32_t* a, const uint32_t* b) {
    asm volatile("mma.sync.aligned.m16n8k16.row.col.f32.bf16.bf16.f32 "
        "{%0,%1,%2,%3}, {%4,%5,%6,%7}, {%8,%9}, {%0,%1,%2,%3};"
        : "+f"(c[0]), "+f"(c[1]), "+f"(c[2]), "+f"(c[3])
        : "r"(a[0]), "r"(a[1]), "r"(a[2]), "r"(a[3]), "r"(b[0]), "r"(b[1]));
}
__device__ __forceinline__ uint32_t sw128(uint32_t off) {
    return off ^ ((off >> 3) & 0x70);
}

// ---------------------------------------------------------------------------
// prep kernels
// ---------------------------------------------------------------------------
__global__ void k_styles(const float* __restrict__ w,
                         const float* __restrict__ affine_w,
                         const float* __restrict__ affine_b) {
    const int b = blockIdx.x, t = threadIdx.x;
    __shared__ float sw[WDIM];
    sw[t] = w[b * WDIM + t];
    __syncthreads();
    const float gain = 1.0f / sqrtf((float)WDIM);
    float m[3];
#pragma unroll
    for (int j0 = 0; j0 < 3; j0++) {
        const int j = j0 * CIN + t;
        const float* __restrict__ row = affine_w + (size_t)j * WDIM;
        float acc = 0.f;
        for (int k = 0; k < WDIM; k++) acc += row[k] * sw[k];
        m[j0] = acc * gain + affine_b[j];
    }
    g_styles[b * CIN + t] = m[0] * m[1] + m[2];
}

__global__ void k_wsq(const float* __restrict__ weight) {
    const int id = blockIdx.x * blockDim.x + threadIdx.x;
    const int cin = id / COUT, cout = id - cin * COUT;
    const float* __restrict__ p = weight + ((size_t)cout * CIN + cin) * 9;
    float s = 0.f;
#pragma unroll
    for (int i = 0; i < 9; i++) { float v = p[i]; s += v * v; }
    g_wsqT[cin * COUT + cout] = s;
}

__global__ void k_dcoefs() {
    const int b = blockIdx.x, t = threadIdx.x;
    __shared__ float s2[CIN];
    const float st = g_styles[b * CIN + t];
    s2[t] = st * st;
    __syncthreads();
    float acc = 0.f;
    for (int cin = 0; cin < CIN; cin++) acc += s2[cin] * g_wsqT[cin * COUT + t];
    g_dcoefs[b * COUT + t] = rsqrtf(acc + 1e-8f);
}

__global__ void k_pack_w(const float* __restrict__ weight) {
    const int co = blockIdx.x, ci = threadIdx.x;
    const float* __restrict__ wp = weight + ((size_t)co * CIN + ci) * 9;
#pragma unroll
    for (int t = 0; t < 9; t++) {
        float v = wp[t];
        __nv_bfloat16 hi = __float2bfloat16(v);
        __nv_bfloat16 lo = __float2bfloat16(v - __bfloat162float(hi));
        size_t o = ((size_t)t * COUT + co) * CIN + ci;
        g_ah[o] = hi; g_al[o] = lo;
    }
}

// pack modulated input + zero the padding ring (fused)
// grid (16, 66, BB), block 256
__global__ void k_pack_x(const float* __restrict__ x) {
    const int b = blockIdx.z, hp = blockIdx.y, cin0 = blockIdx.x * 32;
    const int t = threadIdx.x;
    const __nv_bfloat16 zz = __float2bfloat16(0.f);

    if (hp == 0 || hp == 65) {           // top/bottom pad rows: all zeros
        for (int idx = t; idx < 66 * 32; idx += 256) {
            const int pw = idx >> 5, c = idx & 31;
            size_t o = ((size_t)b * NPIX + hp * PADW + pw) * CIN + cin0 + c;
            g_xh[o] = zz; g_xl[o] = zz;
        }
        return;
    }
    const int h = hp - 1;
    __shared__ float tile[32][65];
    {
        const int w = t & 63, i0 = t >> 6;
#pragma unroll
        for (int j = 0; j < 8; j++) {
            const int ci = i0 * 8 + j;
            tile[ci][w] = x[(((size_t)b * CIN + cin0 + ci) * RES + h) * RES + w];
        }
    }
    if (t < 64) {                         // left/right pad cols
        const int c = t & 31, pw = (t < 32) ? 0 : 65;
        size_t o = ((size_t)b * NPIX + hp * PADW + pw) * CIN + cin0 + c;
        g_xh[o] = zz; g_xl[o] = zz;
    }
    __syncthreads();
    {
        const int c = t & 31, w0 = t >> 5;
        const float st = g_styles[b * CIN + cin0 + c];
        for (int w = w0; w < 64; w += 8) {
            float v = tile[c][w] * st;
            __nv_bfloat16 hi = __float2bfloat16(v);
            __nv_bfloat16 lo = __float2bfloat16(v - __bfloat162float(hi));
            size_t o = ((size_t)b * NPIX + hp * PADW + (w + 1)) * CIN + cin0 + c;
            g_xh[o] = hi; g_xl[o] = lo;
        }
    }
}

// ---------------------------------------------------------------------------
// main conv kernel: mma.sync bf16 implicit GEMM (3-combo hi/lo split)
// CTA: M=128 couts x N=128 pixels, 8 warps, warp tile 64x32
// K-loop: 9 taps x 8 cin-chunks of 64 = 72 iters
// 3-stage cp.async pipeline, ONE __syncthreads per iteration
// ---------------------------------------------------------------------------
#define OFF_AH  0
#define OFF_AL  16384
#define OFF_BH  32768
#define OFF_BL  49152
#define STAGE   65536
#define NSTG    3
#define SMEM_DYN (NSTG * STAGE)

extern __shared__ __align__(1024) char smem[];

__global__ void __launch_bounds__(256, 1)
k_conv(const float* __restrict__ bias,
       const float* __restrict__ noise_const,
       const float* __restrict__ noise_strength,
       float* __restrict__ out) {
    const int tid   = threadIdx.x;
    const int wid   = tid >> 5;
    const int lid   = tid & 31;
    const int ptile = blockIdx.x;            // 0..31 (128 pixels = 2 rows each)
    const int cout0 = blockIdx.y * 128;      // 0..3
    const int b     = blockIdx.z;            // batch
    const int wm    = wid >> 2;              // 0..1  (M warp)
    const int wn    = wid & 3;               // 0..3  (N warp)

    const uint32_t sb = smem_u32(smem);

    // ---- loader invariants: 256 threads = 128 rows x {hi,lo} plane
    const int rowid = tid & 127;
    const bool hi_plane = (tid < 128);
    const __nv_bfloat16* aplane = hi_plane ? g_ah : g_al;
    const __nv_bfloat16* xplane = hi_plane ? g_xh : g_xl;
    const uint32_t offA = hi_plane ? OFF_AH : OFF_AL;
    const uint32_t offB = hi_plane ? OFF_BH : OFF_BL;

    const int gp = ptile * 128 + rowid;            // global pixel for B row
    const int bh_ = gp >> 6, bw_ = gp & 63;
    const size_t pixrow = (size_t)b * NPIX + bh_ * PADW + bw_;
    const size_t arow   = (size_t)(cout0 + rowid) * CIN;

    uint32_t sw[8];
#pragma unroll
    for (int sg = 0; sg < 8; sg++) sw[sg] = sw128((uint32_t)(rowid * 128 + sg * 16));

    // ---- ldmatrix per-lane base offsets
    uint32_t aoff[4], boff[4];
#pragma unroll
    for (int mt = 0; mt < 4; mt++)
        aoff[mt] = (uint32_t)((wm * 64 + mt * 16 + (lid & 15)) << 7) + ((lid >> 4) << 4);
#pragma unroll
    for (int nt = 0; nt < 4; nt++)
        boff[nt] = (uint32_t)((wn * 32 + nt * 8 + (lid & 7)) << 7) + (((lid >> 3) & 1) << 4);

    float acc[4][4][4];
#pragma unroll
    for (int mt = 0; mt < 4; mt++)
#pragma unroll
        for (int nt = 0; nt < 4; nt++)
#pragma unroll
            for (int i = 0; i < 4; i++) acc[mt][nt][i] = 0.f;

    // ---- stage loader (slot = it % 3)
    auto load_stage = [&](int it) {
        const int tap = it >> 3, cin0 = (it & 7) << 6;
        const int dh = tap / 3, dw = tap - dh * 3;
        const uint32_t stg = sb + (uint32_t)(it % NSTG) * STAGE;
        const char* asrc = (const char*)(aplane + ((size_t)tap * COUT * CIN + arow + cin0));
        const char* bsrc = (const char*)(xplane + ((pixrow + dh * PADW + dw) * CIN + cin0));
        const uint32_t da = stg + offA, db = stg + offB;
#pragma unroll
        for (int sg = 0; sg < 8; sg++) {
            cpa16(da + sw[sg], asrc + sg * 16);
            cpa16(db + sw[sg], bsrc + sg * 16);
        }
        CP_COMMIT();
    };

    load_stage(0);
    load_stage(1);

#pragma unroll 1
    for (int it = 0; it < 72; it++) {
        if (it < 71) CP_WAIT1(); else CP_WAIT0();   // slot it%3 ready
        __syncthreads();                             // all warps done with slot (it-1)%3
        if (it + 2 < 72) load_stage(it + 2);         // overwrite slot (it-1)%3: safe

        const uint32_t stgA = sb + (uint32_t)(it % NSTG) * STAGE + OFF_AH;
        const uint32_t stgB = sb + (uint32_t)(it % NSTG) * STAGE + OFF_BH;

#pragma unroll
        for (int kk = 0; kk < 4; kk++) {
            uint32_t ah[4][4], al[4][4];
#pragma unroll
            for (int mt = 0; mt < 4; mt++) {
                const uint32_t ad = stgA + sw128(aoff[mt] + kk * 32);
                ldsm4(ah[mt], ad);
                ldsm4(al[mt], ad + 16384);
            }
#pragma unroll
            for (int nt = 0; nt < 4; nt++) {
                uint32_t bhf[2], blf[2];
                const uint32_t bd = stgB + sw128(boff[nt] + kk * 32);
                ldsm2(bhf, bd);
                ldsm2(blf, bd + 16384);
#pragma unroll
                for (int mt = 0; mt < 4; mt++) {
                    mma_bf16(acc[mt][nt], ah[mt], bhf);   // hi*hi
                    mma_bf16(acc[mt][nt], al[mt], bhf);   // lo*hi
                    mma_bf16(acc[mt][nt], ah[mt], blf);   // hi*lo
                }
            }
        }
    }

    // ---- epilogue: demodulate, noise, bias, lrelu*sqrt(2), float2 stores
    const int g = lid >> 2, t2 = (lid & 3) * 2;
    const float ns = noise_strength[0];
    float nz[4][2];
    int hh[4], ww[4];
#pragma unroll
    for (int nt = 0; nt < 4; nt++) {
        const int n = ptile * 128 + wn * 32 + nt * 8 + t2;
        hh[nt] = n >> 6; ww[nt] = n & 63;
        nz[nt][0] = noise_const[hh[nt] * RES + ww[nt]] * ns;
        nz[nt][1] = noise_const[hh[nt] * RES + ww[nt] + 1] * ns;
    }
#pragma unroll
    for (int mt = 0; mt < 4; mt++) {
#pragma unroll
        for (int rr = 0; rr < 2; rr++) {
            const int co = cout0 + wm * 64 + mt * 16 + g + rr * 8;
            const float dc = g_dcoefs[b * COUT + co];
            const float bi = bias[co];
#pragma unroll
            for (int nt = 0; nt < 4; nt++) {
                float v0 = acc[mt][nt][rr * 2 + 0] * dc + nz[nt][0] + bi;
                float v1 = acc[mt][nt][rr * 2 + 1] * dc + nz[nt][1] + bi;
                v0 = (v0 > 0.f ? v0 : 0.2f * v0) * 1.4142135623730951f;
                v1 = (v1 > 0.f ? v1 : 0.2f * v1) * 1.4142135623730951f;
                float2* o = (float2*)&out[(((size_t)b * COUT + co) * RES + hh[nt]) * RES + ww[nt]];
                *o = make_float2(v0, v1);
            }
        }
    }
}

// ---------------------------------------------------------------------------
// launch (6 launches total -> ncu -s 5 profiles k_conv)
// ---------------------------------------------------------------------------
extern "C" void kernel_launch(void* const* d_in, const int* in_sizes, int n_in,
                              void* d_out, int out_size) {
    (void)in_sizes; (void)n_in; (void)out_size;
    const float* x              = (const float*)d_in[0];
    const float* w              = (const float*)d_in[1];
    const float* affine_w       = (const float*)d_in[2];
    const float* affine_b       = (const float*)d_in[3];
    const float* weight         = (const float*)d_in[4];
    const float* bias           = (const float*)d_in[5];
    const float* noise_const    = (const float*)d_in[6];
    const float* noise_strength = (const float*)d_in[7];
    float* out = (float*)d_out;

    cudaFuncSetAttribute(k_conv, cudaFuncAttributeMaxDynamicSharedMemorySize, SMEM_DYN);

    k_styles<<<BB, 512>>>(w, affine_w, affine_b);
    k_wsq<<<(CIN * COUT) / 256, 256>>>(weight);
    k_dcoefs<<<BB, 512>>>();
    k_pack_w<<<COUT, CIN>>>(weight);
    k_pack_x<<<dim3(16, 66, BB), 256>>>(x);

    dim3 grid(32, COUT / 128, BB);
    k_conv<<<grid, 256, SMEM_DYN>>>(bias, noise_const, noise_strength, out);
}

// round 6
// speedup vs baseline: 1.0057x; 1.0057x over previous
#include <cuda_runtime.h>
#include <cuda_bf16.h>
#include <cstdint>

#define BB    16
#define CIN   512
#define COUT  512
#define RES   64
#define WDIM  512
#define PADW  66
#define NPIX  (PADW * PADW)

// ---------------------------------------------------------------------------
// device scratch (static globals — no allocations allowed)
// ---------------------------------------------------------------------------
__device__ float g_styles[BB * CIN];
__device__ float g_dcoefs[BB * COUT];
// packed weights: [tap][cout][cin], bf16 hi/lo planes
__device__ __align__(1024) __nv_bfloat16 g_ah[9ull * COUT * CIN];
__device__ __align__(1024) __nv_bfloat16 g_al[9ull * COUT * CIN];
// packed modulated input: [b][padded pixel][cin], bf16 hi/lo planes
__device__ __align__(1024) __nv_bfloat16 g_xh[(size_t)BB * NPIX * CIN];
__device__ __align__(1024) __nv_bfloat16 g_xl[(size_t)BB * NPIX * CIN];

// ---------------------------------------------------------------------------
// PTX helpers (baseline compute_103-safe)
// ---------------------------------------------------------------------------
__device__ __forceinline__ uint32_t smem_u32(const void* p) {
    uint32_t a;
    asm("{ .reg .u64 t; cvta.to.shared.u64 t, %1; cvt.u32.u64 %0, t; }" : "=r"(a) : "l"(p));
    return a;
}
__device__ __forceinline__ void cpa16(uint32_t dst, const void* src) {
    asm volatile("cp.async.cg.shared.global [%0], [%1], 16;" :: "r"(dst), "l"(src));
}
#define CP_COMMIT()  asm volatile("cp.async.commit_group;" ::: "memory")
#define CP_WAIT1()   asm volatile("cp.async.wait_group 1;" ::: "memory")
#define CP_WAIT0()   asm volatile("cp.async.wait_group 0;" ::: "memory")

__device__ __forceinline__ void ldsm4(uint32_t* r, uint32_t a) {
    asm volatile("ldmatrix.sync.aligned.m8n8.x4.shared.b16 {%0,%1,%2,%3}, [%4];"
        : "=r"(r[0]), "=r"(r[1]), "=r"(r[2]), "=r"(r[3]) : "r"(a));
}
__device__ __forceinline__ void ldsm2(uint32_t* r, uint32_t a) {
    asm volatile("ldmatrix.sync.aligned.m8n8.x2.shared.b16 {%0,%1}, [%2];"
        : "=r"(r[0]), "=r"(r[1]) : "r"(a));
}
__device__ __forceinline__ void mma_bf16(float* c, const uint32_t* a, const uint32_t* b) {
    asm volatile("mma.sync.aligned.m16n8k16.row.col.f32.bf16.bf16.f32 "
        "{%0,%1,%2,%3}, {%4,%5,%6,%7}, {%8,%9}, {%0,%1,%2,%3};"
        : "+f"(c[0]), "+f"(c[1]), "+f"(c[2]), "+f"(c[3])
        : "r"(a[0]), "r"(a[1]), "r"(a[2]), "r"(a[3]), "r"(b[0]), "r"(b[1]));
}
__device__ __forceinline__ uint32_t sw128(uint32_t off) {
    return off ^ ((off >> 3) & 0x70);
}

// ---------------------------------------------------------------------------
// prep kernel 1: styles
// ---------------------------------------------------------------------------
__global__ void k_styles(const float* __restrict__ w,
                         const float* __restrict__ affine_w,
                         const float* __restrict__ affine_b) {
    const int b = blockIdx.x, t = threadIdx.x;
    __shared__ float sw[WDIM];
    sw[t] = w[b * WDIM + t];
    __syncthreads();
    const float gain = 1.0f / sqrtf((float)WDIM);
    float m[3];
#pragma unroll
    for (int j0 = 0; j0 < 3; j0++) {
        const int j = j0 * CIN + t;
        const float* __restrict__ row = affine_w + (size_t)j * WDIM;
        float acc = 0.f;
        for (int k = 0; k < WDIM; k++) acc += row[k] * sw[k];
        m[j0] = acc * gain + affine_b[j];
    }
    g_styles[b * CIN + t] = m[0] * m[1] + m[2];
}

// ---------------------------------------------------------------------------
// prep kernel 2 (fused): pack weights hi/lo + wsq + dcoefs
// grid = COUT (512 blocks), block = 512 (one thread per cin)
// ---------------------------------------------------------------------------
__global__ void k_prep(const float* __restrict__ weight) {
    const int co = blockIdx.x, ci = threadIdx.x;
    const float* __restrict__ wp = weight + ((size_t)co * CIN + ci) * 9;
    float s = 0.f;
#pragma unroll
    for (int t = 0; t < 9; t++) {
        const float v = wp[t];
        s += v * v;
        __nv_bfloat16 hi = __float2bfloat16(v);
        __nv_bfloat16 lo = __float2bfloat16(v - __bfloat162float(hi));
        const size_t o = ((size_t)t * COUT + co) * CIN + ci;
        g_ah[o] = hi; g_al[o] = lo;
    }
    // dcoefs[b][co] = rsqrt( sum_ci styles^2 * s )
    float p[BB];
#pragma unroll
    for (int b = 0; b < BB; b++) {
        const float st = g_styles[b * CIN + ci];
        p[b] = st * st * s;
    }
#pragma unroll
    for (int b = 0; b < BB; b++)
#pragma unroll
        for (int off = 16; off > 0; off >>= 1)
            p[b] += __shfl_xor_sync(0xFFFFFFFFu, p[b], off);
    __shared__ float red[BB][17];
    const int wrp = ci >> 5, lane = ci & 31;
    if (lane == 0)
#pragma unroll
        for (int b = 0; b < BB; b++) red[b][wrp] = p[b];
    __syncthreads();
    if (ci < BB) {
        float acc = 0.f;
#pragma unroll
        for (int k = 0; k < 16; k++) acc += red[ci][k];
        g_dcoefs[ci * COUT + co] = rsqrtf(acc + 1e-8f);
    }
}

// ---------------------------------------------------------------------------
// prep kernel 3: pack modulated input + padding ring (fused)
// grid (16, 66, BB), block 256
// ---------------------------------------------------------------------------
__global__ void k_pack_x(const float* __restrict__ x) {
    const int b = blockIdx.z, hp = blockIdx.y, cin0 = blockIdx.x * 32;
    const int t = threadIdx.x;
    const __nv_bfloat16 zz = __float2bfloat16(0.f);

    if (hp == 0 || hp == 65) {
        for (int idx = t; idx < 66 * 32; idx += 256) {
            const int pw = idx >> 5, c = idx & 31;
            size_t o = ((size_t)b * NPIX + hp * PADW + pw) * CIN + cin0 + c;
            g_xh[o] = zz; g_xl[o] = zz;
        }
        return;
    }
    const int h = hp - 1;
    __shared__ float tile[32][65];
    {
        const int w = t & 63, i0 = t >> 6;
#pragma unroll
        for (int j = 0; j < 8; j++) {
            const int ci = i0 * 8 + j;
            tile[ci][w] = x[(((size_t)b * CIN + cin0 + ci) * RES + h) * RES + w];
        }
    }
    if (t < 64) {
        const int c = t & 31, pw = (t < 32) ? 0 : 65;
        size_t o = ((size_t)b * NPIX + hp * PADW + pw) * CIN + cin0 + c;
        g_xh[o] = zz; g_xl[o] = zz;
    }
    __syncthreads();
    {
        const int c = t & 31, w0 = t >> 5;
        const float st = g_styles[b * CIN + cin0 + c];
        for (int w = w0; w < 64; w += 8) {
            float v = tile[c][w] * st;
            __nv_bfloat16 hi = __float2bfloat16(v);
            __nv_bfloat16 lo = __float2bfloat16(v - __bfloat162float(hi));
            size_t o = ((size_t)b * NPIX + hp * PADW + (w + 1)) * CIN + cin0 + c;
            g_xh[o] = hi; g_xl[o] = lo;
        }
    }
}

// ---------------------------------------------------------------------------
// main conv kernel: mma.sync bf16 implicit GEMM (3-combo hi/lo split)
// CTA: M=128 couts x N=128 pixels, 512 threads / 16 warps, warp tile 32x32
// K-loop: 72 iters, 3-stage cp.async pipeline, combo-major MMA ordering
// ---------------------------------------------------------------------------
#define OFF_AH  0
#define OFF_AL  16384
#define OFF_BH  32768
#define OFF_BL  49152
#define STAGE   65536
#define NSTG    3
#define SMEM_DYN (NSTG * STAGE)

extern __shared__ __align__(1024) char smem[];

__global__ void __launch_bounds__(512, 1)
k_conv(const float* __restrict__ bias,
       const float* __restrict__ noise_const,
       const float* __restrict__ noise_strength,
       float* __restrict__ out) {
    const int tid   = threadIdx.x;
    const int wid   = tid >> 5;
    const int lid   = tid & 31;
    const int ptile = blockIdx.x;            // 0..31 (128 pixels)
    const int cout0 = blockIdx.y * 128;      // 0..3
    const int b     = blockIdx.z;
    const int wm    = wid >> 2;              // 0..3 (M warp: 32 rows)
    const int wn    = wid & 3;               // 0..3 (N warp: 32 cols)

    const uint32_t sb = smem_u32(smem);

    // ---- loader invariants: 512 threads = 4 planes x 128 rows
    const int quarter = tid >> 7;            // 0:A-hi 1:A-lo 2:B-hi 3:B-lo
    const int rowid   = tid & 127;
    const bool isA    = quarter < 2;
    const __nv_bfloat16* plane =
        (quarter == 0) ? g_ah : (quarter == 1) ? g_al : (quarter == 2) ? g_xh : g_xl;
    const uint32_t doff = (uint32_t)quarter * 16384u;

    const int gp = ptile * 128 + rowid;
    const int bh_ = gp >> 6, bw_ = gp & 63;
    const size_t rowoff = isA ? (size_t)(cout0 + rowid) * CIN
                              : ((size_t)b * NPIX + bh_ * PADW + bw_) * CIN;

    uint32_t sw[8];
#pragma unroll
    for (int sg = 0; sg < 8; sg++) sw[sg] = sw128((uint32_t)(rowid * 128 + sg * 16));

    // ---- ldmatrix per-lane base offsets
    uint32_t aoff[2], boff[4];
#pragma unroll
    for (int mt = 0; mt < 2; mt++)
        aoff[mt] = (uint32_t)((wm * 32 + mt * 16 + (lid & 15)) << 7) + ((lid >> 4) << 4);
#pragma unroll
    for (int nt = 0; nt < 4; nt++)
        boff[nt] = (uint32_t)((wn * 32 + nt * 8 + (lid & 7)) << 7) + (((lid >> 3) & 1) << 4);

    float acc[2][4][4];
#pragma unroll
    for (int mt = 0; mt < 2; mt++)
#pragma unroll
        for (int nt = 0; nt < 4; nt++)
#pragma unroll
            for (int i = 0; i < 4; i++) acc[mt][nt][i] = 0.f;

    // ---- stage loader (slot = it % 3); each thread loads one 128B row
    auto load_stage = [&](int it) {
        const int tap = it >> 3, cin0 = (it & 7) << 6;
        const int dh = tap / 3, dw = tap - dh * 3;
        const size_t off = isA ? ((size_t)tap * COUT * CIN + rowoff + cin0)
                               : (rowoff + (size_t)(dh * PADW + dw) * CIN + cin0);
        const char* src = (const char*)(plane + off);
        const uint32_t dst = sb + (uint32_t)(it % NSTG) * STAGE + doff;
#pragma unroll
        for (int sg = 0; sg < 8; sg++) cpa16(dst + sw[sg], src + sg * 16);
        CP_COMMIT();
    };

    load_stage(0);
    load_stage(1);

#pragma unroll 1
    for (int it = 0; it < 72; it++) {
        if (it < 71) CP_WAIT1(); else CP_WAIT0();
        __syncthreads();
        if (it + 2 < 72) load_stage(it + 2);

        const uint32_t stgA = sb + (uint32_t)(it % NSTG) * STAGE + OFF_AH;
        const uint32_t stgB = sb + (uint32_t)(it % NSTG) * STAGE + OFF_BH;

#pragma unroll
        for (int kk = 0; kk < 4; kk++) {
            uint32_t ah[2][4], al[2][4];
#pragma unroll
            for (int mt = 0; mt < 2; mt++) {
                const uint32_t ad = stgA + sw128(aoff[mt] + kk * 32);
                ldsm4(ah[mt], ad);
                ldsm4(al[mt], ad + 16384);
            }
            uint32_t bh[4][2], bl[4][2];
#pragma unroll
            for (int nt = 0; nt < 4; nt++) {
                const uint32_t bd = stgB + sw128(boff[nt] + kk * 32);
                ldsm2(bh[nt], bd);
                ldsm2(bl[nt], bd + 16384);
            }
            // combo-major: same-accumulator reuse distance = 8 MMAs
#pragma unroll
            for (int nt = 0; nt < 4; nt++)
#pragma unroll
                for (int mt = 0; mt < 2; mt++)
                    mma_bf16(acc[mt][nt], ah[mt], bh[nt]);   // hi*hi
#pragma unroll
            for (int nt = 0; nt < 4; nt++)
#pragma unroll
                for (int mt = 0; mt < 2; mt++)
                    mma_bf16(acc[mt][nt], al[mt], bh[nt]);   // lo*hi
#pragma unroll
            for (int nt = 0; nt < 4; nt++)
#pragma unroll
                for (int mt = 0; mt < 2; mt++)
                    mma_bf16(acc[mt][nt], ah[mt], bl[nt]);   // hi*lo
        }
    }

    // ---- epilogue: demodulate, noise, bias, lrelu*sqrt(2), float2 stores
    const int g = lid >> 2, t2 = (lid & 3) * 2;
    const float ns = noise_strength[0];
    float nz[4][2];
    int hh[4], ww[4];
#pragma unroll
    for (int nt = 0; nt < 4; nt++) {
        const int n = ptile * 128 + wn * 32 + nt * 8 + t2;
        hh[nt] = n >> 6; ww[nt] = n & 63;
        nz[nt][0] = noise_const[hh[nt] * RES + ww[nt]] * ns;
        nz[nt][1] = noise_const[hh[nt] * RES + ww[nt] + 1] * ns;
    }
#pragma unroll
    for (int mt = 0; mt < 2; mt++) {
#pragma unroll
        for (int rr = 0; rr < 2; rr++) {
            const int co = cout0 + wm * 32 + mt * 16 + g + rr * 8;
            const float dc = g_dcoefs[b * COUT + co];
            const float bi = bias[co];
#pragma unroll
            for (int nt = 0; nt < 4; nt++) {
                float v0 = acc[mt][nt][rr * 2 + 0] * dc + nz[nt][0] + bi;
                float v1 = acc[mt][nt][rr * 2 + 1] * dc + nz[nt][1] + bi;
                v0 = (v0 > 0.f ? v0 : 0.2f * v0) * 1.4142135623730951f;
                v1 = (v1 > 0.f ? v1 : 0.2f * v1) * 1.4142135623730951f;
                float2* o = (float2*)&out[(((size_t)b * COUT + co) * RES + hh[nt]) * RES + ww[nt]];
                *o = make_float2(v0, v1);
            }
        }
    }
}

// ---------------------------------------------------------------------------
// launch: exactly 4 kernels (harness prepends 2 launches -> ncu -s 5 = k_conv)
// ---------------------------------------------------------------------------
extern "C" void kernel_launch(void* const* d_in, const int* in_sizes, int n_in,
                              void* d_out, int out_size) {
    (void)in_sizes; (void)n_in; (void)out_size;
    const float* x              = (const float*)d_in[0];
    const float* w              = (const float*)d_in[1];
    const float* affine_w       = (const float*)d_in[2];
    const float* affine_b       = (const float*)d_in[3];
    const float* weight         = (const float*)d_in[4];
    const float* bias           = (const float*)d_in[5];
    const float* noise_const    = (const float*)d_in[6];
    const float* noise_strength = (const float*)d_in[7];
    float* out = (float*)d_out;

    cudaFuncSetAttribute(k_conv, cudaFuncAttributeMaxDynamicSharedMemorySize, SMEM_DYN);

    k_styles<<<BB, 512>>>(w, affine_w, affine_b);
    k_prep<<<COUT, 512>>>(weight);
    k_pack_x<<<dim3(16, 66, BB), 256>>>(x);

    dim3 grid(32, COUT / 128, BB);
    k_conv<<<grid, 512, SMEM_DYN>>>(bias, noise_const, noise_strength, out);
}

// round 7
// speedup vs baseline: 1.1748x; 1.1682x over previous
#include <cuda_runtime.h>
#include <cuda_bf16.h>
#include <cstdint>

#define BB    16
#define CIN   512
#define COUT  512
#define RES   64
#define WDIM  512
#define PADW  66
#define NPIX  (PADW * PADW)

// ---------------------------------------------------------------------------
// device scratch (static globals — no allocations allowed)
// ---------------------------------------------------------------------------
__device__ float g_styles[BB * CIN];
__device__ float g_dcoefs[BB * COUT];
__device__ __align__(1024) __nv_bfloat16 g_ah[9ull * COUT * CIN];
__device__ __align__(1024) __nv_bfloat16 g_al[9ull * COUT * CIN];
__device__ __align__(1024) __nv_bfloat16 g_xh[(size_t)BB * NPIX * CIN];
__device__ __align__(1024) __nv_bfloat16 g_xl[(size_t)BB * NPIX * CIN];

// ---------------------------------------------------------------------------
// PTX helpers (baseline compute_103-safe)
// ---------------------------------------------------------------------------
__device__ __forceinline__ uint32_t smem_u32(const void* p) {
    uint32_t a;
    asm("{ .reg .u64 t; cvta.to.shared.u64 t, %1; cvt.u32.u64 %0, t; }" : "=r"(a) : "l"(p));
    return a;
}
__device__ __forceinline__ void cpa16(uint32_t dst, const void* src) {
    asm volatile("cp.async.cg.shared.global [%0], [%1], 16;" :: "r"(dst), "l"(src));
}
#define CP_COMMIT()  asm volatile("cp.async.commit_group;" ::: "memory")
#define CP_WAIT0()   asm volatile("cp.async.wait_group 0;" ::: "memory")

__device__ __forceinline__ void ldsm4(uint32_t* r, uint32_t a) {
    asm volatile("ldmatrix.sync.aligned.m8n8.x4.shared.b16 {%0,%1,%2,%3}, [%4];"
        : "=r"(r[0]), "=r"(r[1]), "=r"(r[2]), "=r"(r[3]) : "r"(a));
}
__device__ __forceinline__ void mma_bf16(float* c, const uint32_t* a, const uint32_t* b) {
    asm volatile("mma.sync.aligned.m16n8k16.row.col.f32.bf16.bf16.f32 "
        "{%0,%1,%2,%3}, {%4,%5,%6,%7}, {%8,%9}, {%0,%1,%2,%3};"
        : "+f"(c[0]), "+f"(c[1]), "+f"(c[2]), "+f"(c[3])
        : "r"(a[0]), "r"(a[1]), "r"(a[2]), "r"(a[3]), "r"(b[0]), "r"(b[1]));
}
__device__ __forceinline__ uint32_t sw128(uint32_t off) {
    return off ^ ((off >> 3) & 0x70);
}

// ---------------------------------------------------------------------------
// prep kernel 1: styles
// ---------------------------------------------------------------------------
__global__ void k_styles(const float* __restrict__ w,
                         const float* __restrict__ affine_w,
                         const float* __restrict__ affine_b) {
    const int b = blockIdx.x, t = threadIdx.x;
    __shared__ float sw[WDIM];
    sw[t] = w[b * WDIM + t];
    __syncthreads();
    const float gain = 1.0f / sqrtf((float)WDIM);
    float m[3];
#pragma unroll
    for (int j0 = 0; j0 < 3; j0++) {
        const int j = j0 * CIN + t;
        const float* __restrict__ row = affine_w + (size_t)j * WDIM;
        float acc = 0.f;
        for (int k = 0; k < WDIM; k++) acc += row[k] * sw[k];
        m[j0] = acc * gain + affine_b[j];
    }
    g_styles[b * CIN + t] = m[0] * m[1] + m[2];
}

// ---------------------------------------------------------------------------
// prep kernel 2 (fused): pack weights hi/lo + wsq + dcoefs
// ---------------------------------------------------------------------------
__global__ void k_prep(const float* __restrict__ weight) {
    const int co = blockIdx.x, ci = threadIdx.x;
    const float* __restrict__ wp = weight + ((size_t)co * CIN + ci) * 9;
    float s = 0.f;
#pragma unroll
    for (int t = 0; t < 9; t++) {
        const float v = wp[t];
        s += v * v;
        __nv_bfloat16 hi = __float2bfloat16(v);
        __nv_bfloat16 lo = __float2bfloat16(v - __bfloat162float(hi));
        const size_t o = ((size_t)t * COUT + co) * CIN + ci;
        g_ah[o] = hi; g_al[o] = lo;
    }
    float p[BB];
#pragma unroll
    for (int b = 0; b < BB; b++) {
        const float st = g_styles[b * CIN + ci];
        p[b] = st * st * s;
    }
#pragma unroll
    for (int b = 0; b < BB; b++)
#pragma unroll
        for (int off = 16; off > 0; off >>= 1)
            p[b] += __shfl_xor_sync(0xFFFFFFFFu, p[b], off);
    __shared__ float red[BB][17];
    const int wrp = ci >> 5, lane = ci & 31;
    if (lane == 0)
#pragma unroll
        for (int b = 0; b < BB; b++) red[b][wrp] = p[b];
    __syncthreads();
    if (ci < BB) {
        float acc = 0.f;
#pragma unroll
        for (int k = 0; k < 16; k++) acc += red[ci][k];
        g_dcoefs[ci * COUT + co] = rsqrtf(acc + 1e-8f);
    }
}

// ---------------------------------------------------------------------------
// prep kernel 3: pack modulated input + padding ring (fused)
// ---------------------------------------------------------------------------
__global__ void k_pack_x(const float* __restrict__ x) {
    const int b = blockIdx.z, hp = blockIdx.y, cin0 = blockIdx.x * 32;
    const int t = threadIdx.x;
    const __nv_bfloat16 zz = __float2bfloat16(0.f);

    if (hp == 0 || hp == 65) {
        for (int idx = t; idx < 66 * 32; idx += 256) {
            const int pw = idx >> 5, c = idx & 31;
            size_t o = ((size_t)b * NPIX + hp * PADW + pw) * CIN + cin0 + c;
            g_xh[o] = zz; g_xl[o] = zz;
        }
        return;
    }
    const int h = hp - 1;
    __shared__ float tile[32][65];
    {
        const int w = t & 63, i0 = t >> 6;
#pragma unroll
        for (int j = 0; j < 8; j++) {
            const int ci = i0 * 8 + j;
            tile[ci][w] = x[(((size_t)b * CIN + cin0 + ci) * RES + h) * RES + w];
        }
    }
    if (t < 64) {
        const int c = t & 31, pw = (t < 32) ? 0 : 65;
        size_t o = ((size_t)b * NPIX + hp * PADW + pw) * CIN + cin0 + c;
        g_xh[o] = zz; g_xl[o] = zz;
    }
    __syncthreads();
    {
        const int c = t & 31, w0 = t >> 5;
        const float st = g_styles[b * CIN + cin0 + c];
        for (int w = w0; w < 64; w += 8) {
            float v = tile[c][w] * st;
            __nv_bfloat16 hi = __float2bfloat16(v);
            __nv_bfloat16 lo = __float2bfloat16(v - __bfloat162float(hi));
            size_t o = ((size_t)b * NPIX + hp * PADW + (w + 1)) * CIN + cin0 + c;
            g_xh[o] = hi; g_xl[o] = lo;
        }
    }
}

// ---------------------------------------------------------------------------
// main conv kernel: mma.sync bf16 implicit GEMM (3-combo hi/lo split)
// CTA: M=128 couts x N=256 pixels, 256 threads / 8 warps, warp tile 64x64
// K-loop: 72 iters, 2-stage cp.async pipeline, 1 sync/iter
// ---------------------------------------------------------------------------
#define OFF_AH  0
#define OFF_AL  16384
#define OFF_BH  32768
#define OFF_BL  65536
#define STAGE   98304
#define SMEM_DYN (2 * STAGE)

extern __shared__ __align__(1024) char smem[];

__global__ void __launch_bounds__(256, 1)
k_conv(const float* __restrict__ bias,
       const float* __restrict__ noise_const,
       const float* __restrict__ noise_strength,
       float* __restrict__ out) {
    const int tid   = threadIdx.x;
    const int wid   = tid >> 5;
    const int lid   = tid & 31;
    const int ptile = blockIdx.x;            // 0..15 (256 pixels = 4 rows each)
    const int cout0 = blockIdx.y * 128;      // 0..3
    const int b     = blockIdx.z;
    const int wm    = wid >> 2;              // 0..1 (M warp: 64 rows)
    const int wn    = wid & 3;               // 0..3 (N warp: 64 pixels)

    const uint32_t sb = smem_u32(smem);

    // ---- loader invariants: each thread loads 3 rows of 128B per stage
    //      A plane row (t>>7 selects hi/lo, t&127 = cout row), B-h row t, B-l row t
    const int arow_l = tid & 127;
    const uint32_t aoffP = (tid < 128) ? OFF_AH : OFF_AL;
    const __nv_bfloat16* aplane = (tid < 128) ? g_ah : g_al;
    const size_t arow = (size_t)(cout0 + arow_l) * CIN;

    const int gp = ptile * 256 + tid;        // B pixel row handled by this thread
    const size_t browoff = ((size_t)b * NPIX + (gp >> 6) * PADW + (gp & 63)) * CIN;

    uint32_t swA[8], swB[8];
#pragma unroll
    for (int sg = 0; sg < 8; sg++) {
        swA[sg] = sw128((uint32_t)(arow_l * 128 + sg * 16));
        swB[sg] = sw128((uint32_t)(tid * 128 + sg * 16));
    }

    // ---- ldmatrix per-lane base offsets
    uint32_t aoff[4], boff[4];
#pragma unroll
    for (int mt = 0; mt < 4; mt++)
        aoff[mt] = (uint32_t)((wm * 64 + mt * 16 + (lid & 15)) << 7) + ((lid >> 4) << 4);
#pragma unroll
    for (int p = 0; p < 4; p++)
        boff[p] = (uint32_t)((wn * 64 + p * 16 + ((lid >> 4) & 1) * 8 + (lid & 7)) << 7)
                + (((lid >> 3) & 1) << 4);

    float acc[4][8][4];
#pragma unroll
    for (int mt = 0; mt < 4; mt++)
#pragma unroll
        for (int nt = 0; nt < 8; nt++)
#pragma unroll
            for (int i = 0; i < 4; i++) acc[mt][nt][i] = 0.f;

    // ---- stage loader (slot = it & 1): 24 cp.async per thread
    auto load_stage = [&](int it) {
        const int tap = it >> 3, cin0 = (it & 7) << 6;
        const int dh = tap / 3, dw = tap - dh * 3;
        const uint32_t stg = sb + (uint32_t)(it & 1) * STAGE;
        const char* asrc = (const char*)(aplane + ((size_t)tap * COUT * CIN + arow + cin0));
        const char* bhs  = (const char*)(g_xh + (browoff + (size_t)(dh * PADW + dw) * CIN + cin0));
        const char* bls  = (const char*)(g_xl + (browoff + (size_t)(dh * PADW + dw) * CIN + cin0));
        const uint32_t da = stg + aoffP, dbh = stg + OFF_BH, dbl = stg + OFF_BL;
#pragma unroll
        for (int sg = 0; sg < 8; sg++) {
            cpa16(da  + swA[sg], asrc + sg * 16);
            cpa16(dbh + swB[sg], bhs + sg * 16);
            cpa16(dbl + swB[sg], bls + sg * 16);
        }
        CP_COMMIT();
    };

    load_stage(0);

#pragma unroll 1
    for (int it = 0; it < 72; it++) {
        CP_WAIT0();            // slot it&1 ready (only group load(it) outstanding)
        __syncthreads();       // everyone done with slot (it+1)&1 (= compute it-1)
        if (it + 1 < 72) load_stage(it + 1);

        const uint32_t stgA = sb + (uint32_t)(it & 1) * STAGE;
        const uint32_t stgB = stgA + OFF_BH;

#pragma unroll
        for (int kk = 0; kk < 4; kk++) {
            uint32_t ah[4][4], al[4][4];
#pragma unroll
            for (int mt = 0; mt < 4; mt++) {
                const uint32_t ad = stgA + sw128(aoff[mt] + kk * 32);
                ldsm4(ah[mt], ad);
                ldsm4(al[mt], ad + 16384);
            }
            // process n-tiles in pairs-of-pairs: 4 n-tiles at a time
#pragma unroll
            for (int half = 0; half < 2; half++) {
                uint32_t bh[2][4], bl[2][4];   // [pair][4 regs = 2 n-tiles]
#pragma unroll
                for (int pp = 0; pp < 2; pp++) {
                    const int p = half * 2 + pp;
                    const uint32_t bd = stgB + sw128(boff[p] + kk * 32);
                    ldsm4(bh[pp], bd);
                    ldsm4(bl[pp], bd + 32768);
                }
                // combo-major over 4 n-tiles x 4 m-tiles: acc reuse distance 16
#pragma unroll
                for (int pp = 0; pp < 2; pp++)
#pragma unroll
                    for (int half2 = 0; half2 < 2; half2++)
#pragma unroll
                        for (int mt = 0; mt < 4; mt++)
                            mma_bf16(acc[mt][half * 4 + pp * 2 + half2],
                                     ah[mt], &bh[pp][half2 * 2]);
#pragma unroll
                for (int pp = 0; pp < 2; pp++)
#pragma unroll
                    for (int half2 = 0; half2 < 2; half2++)
#pragma unroll
                        for (int mt = 0; mt < 4; mt++)
                            mma_bf16(acc[mt][half * 4 + pp * 2 + half2],
                                     al[mt], &bh[pp][half2 * 2]);
#pragma unroll
                for (int pp = 0; pp < 2; pp++)
#pragma unroll
                    for (int half2 = 0; half2 < 2; half2++)
#pragma unroll
                        for (int mt = 0; mt < 4; mt++)
                            mma_bf16(acc[mt][half * 4 + pp * 2 + half2],
                                     ah[mt], &bl[pp][half2 * 2]);
            }
        }
    }

    // ---- epilogue: demodulate, noise, bias, lrelu*sqrt(2), float2 stores
    const int g = lid >> 2, t2 = (lid & 3) * 2;
    const float ns = noise_strength[0];
    float nz[8][2];
    int hh[8], ww[8];
#pragma unroll
    for (int nt = 0; nt < 8; nt++) {
        const int n = ptile * 256 + wn * 64 + nt * 8 + t2;
        hh[nt] = n >> 6; ww[nt] = n & 63;
        nz[nt][0] = noise_const[hh[nt] * RES + ww[nt]] * ns;
        nz[nt][1] = noise_const[hh[nt] * RES + ww[nt] + 1] * ns;
    }
#pragma unroll
    for (int mt = 0; mt < 4; mt++) {
#pragma unroll
        for (int rr = 0; rr < 2; rr++) {
            const int co = cout0 + wm * 64 + mt * 16 + g + rr * 8;
            const float dc = g_dcoefs[b * COUT + co];
            const float bi = bias[co];
#pragma unroll
            for (int nt = 0; nt < 8; nt++) {
                float v0 = acc[mt][nt][rr * 2 + 0] * dc + nz[nt][0] + bi;
                float v1 = acc[mt][nt][rr * 2 + 1] * dc + nz[nt][1] + bi;
                v0 = (v0 > 0.f ? v0 : 0.2f * v0) * 1.4142135623730951f;
                v1 = (v1 > 0.f ? v1 : 0.2f * v1) * 1.4142135623730951f;
                float2* o = (float2*)&out[(((size_t)b * COUT + co) * RES + hh[nt]) * RES + ww[nt]];
                *o = make_float2(v0, v1);
            }
        }
    }
}

// ---------------------------------------------------------------------------
// launch: 4 kernels (ncu -s 5 lands on k_conv)
// ---------------------------------------------------------------------------
extern "C" void kernel_launch(void* const* d_in, const int* in_sizes, int n_in,
                              void* d_out, int out_size) {
    (void)in_sizes; (void)n_in; (void)out_size;
    const float* x              = (const float*)d_in[0];
    const float* w              = (const float*)d_in[1];
    const float* affine_w       = (const float*)d_in[2];
    const float* affine_b       = (const float*)d_in[3];
    const float* weight         = (const float*)d_in[4];
    const float* bias           = (const float*)d_in[5];
    const float* noise_const    = (const float*)d_in[6];
    const float* noise_strength = (const float*)d_in[7];
    float* out = (float*)d_out;

    cudaFuncSetAttribute(k_conv, cudaFuncAttributeMaxDynamicSharedMemorySize, SMEM_DYN);

    k_styles<<<BB, 512>>>(w, affine_w, affine_b);
    k_prep<<<COUT, 512>>>(weight);
    k_pack_x<<<dim3(16, 66, BB), 256>>>(x);

    dim3 grid(16, COUT / 128, BB);
    k_conv<<<grid, 256, SMEM_DYN>>>(bias, noise_const, noise_strength, out);
}

// round 8
// speedup vs baseline: 1.6468x; 1.4018x over previous
#include <cuda_runtime.h>
#include <cuda_fp16.h>
#include <cstdint>

#define BB    16
#define CIN   512
#define COUT  512
#define RES   64
#define WDIM  512
#define PADW  66
#define NPIX  (PADW * PADW)

// ---------------------------------------------------------------------------
// device scratch (static globals — no allocations allowed)
// ---------------------------------------------------------------------------
__device__ float g_styles[BB * CIN];
__device__ float g_dcoefs[BB * COUT];
// packed weights: [tap][cout][cin], fp16 hi/lo planes (split is exact)
__device__ __align__(1024) __half g_ah[9ull * COUT * CIN];
__device__ __align__(1024) __half g_al[9ull * COUT * CIN];
// packed modulated input: [b][padded pixel][cin], single fp16 plane
__device__ __align__(1024) __half g_x[(size_t)BB * NPIX * CIN];

// ---------------------------------------------------------------------------
// PTX helpers (baseline compute_103-safe)
// ---------------------------------------------------------------------------
__device__ __forceinline__ uint32_t smem_u32(const void* p) {
    uint32_t a;
    asm("{ .reg .u64 t; cvta.to.shared.u64 t, %1; cvt.u32.u64 %0, t; }" : "=r"(a) : "l"(p));
    return a;
}
__device__ __forceinline__ void cpa16(uint32_t dst, const void* src) {
    asm volatile("cp.async.cg.shared.global [%0], [%1], 16;" :: "r"(dst), "l"(src));
}
#define CP_COMMIT()  asm volatile("cp.async.commit_group;" ::: "memory")
#define CP_WAIT0()   asm volatile("cp.async.wait_group 0;" ::: "memory")

__device__ __forceinline__ void ldsm4(uint32_t* r, uint32_t a) {
    asm volatile("ldmatrix.sync.aligned.m8n8.x4.shared.b16 {%0,%1,%2,%3}, [%4];"
        : "=r"(r[0]), "=r"(r[1]), "=r"(r[2]), "=r"(r[3]) : "r"(a));
}
__device__ __forceinline__ void mma_f16(float* c, const uint32_t* a, const uint32_t* b) {
    asm volatile("mma.sync.aligned.m16n8k16.row.col.f32.f16.f16.f32 "
        "{%0,%1,%2,%3}, {%4,%5,%6,%7}, {%8,%9}, {%0,%1,%2,%3};"
        : "+f"(c[0]), "+f"(c[1]), "+f"(c[2]), "+f"(c[3])
        : "r"(a[0]), "r"(a[1]), "r"(a[2]), "r"(a[3]), "r"(b[0]), "r"(b[1]));
}
__device__ __forceinline__ uint32_t sw128(uint32_t off) {
    return off ^ ((off >> 3) & 0x70);
}

// ---------------------------------------------------------------------------
// prep kernel 1: styles
// ---------------------------------------------------------------------------
__global__ void k_styles(const float* __restrict__ w,
                         const float* __restrict__ affine_w,
                         const float* __restrict__ affine_b) {
    const int b = blockIdx.x, t = threadIdx.x;
    __shared__ float sw[WDIM];
    sw[t] = w[b * WDIM + t];
    __syncthreads();
    const float gain = 1.0f / sqrtf((float)WDIM);
    float m[3];
#pragma unroll
    for (int j0 = 0; j0 < 3; j0++) {
        const int j = j0 * CIN + t;
        const float* __restrict__ row = affine_w + (size_t)j * WDIM;
        float acc = 0.f;
        for (int k = 0; k < WDIM; k++) acc += row[k] * sw[k];
        m[j0] = acc * gain + affine_b[j];
    }
    g_styles[b * CIN + t] = m[0] * m[1] + m[2];
}

// ---------------------------------------------------------------------------
// prep kernel 2 (fused): pack weights fp16 hi/lo + wsq + dcoefs
// ---------------------------------------------------------------------------
__global__ void k_prep(const float* __restrict__ weight) {
    const int co = blockIdx.x, ci = threadIdx.x;
    const float* __restrict__ wp = weight + ((size_t)co * CIN + ci) * 9;
    float s = 0.f;
#pragma unroll
    for (int t = 0; t < 9; t++) {
        const float v = wp[t];
        s += v * v;
        const __half hi = __float2half(v);
        const __half lo = __float2half(v - __half2float(hi));
        const size_t o = ((size_t)t * COUT + co) * CIN + ci;
        g_ah[o] = hi; g_al[o] = lo;
    }
    float p[BB];
#pragma unroll
    for (int b = 0; b < BB; b++) {
        const float st = g_styles[b * CIN + ci];
        p[b] = st * st * s;
    }
#pragma unroll
    for (int b = 0; b < BB; b++)
#pragma unroll
        for (int off = 16; off > 0; off >>= 1)
            p[b] += __shfl_xor_sync(0xFFFFFFFFu, p[b], off);
    __shared__ float red[BB][17];
    const int wrp = ci >> 5, lane = ci & 31;
    if (lane == 0)
#pragma unroll
        for (int b = 0; b < BB; b++) red[b][wrp] = p[b];
    __syncthreads();
    if (ci < BB) {
        float acc = 0.f;
#pragma unroll
        for (int k = 0; k < 16; k++) acc += red[ci][k];
        g_dcoefs[ci * COUT + co] = rsqrtf(acc + 1e-8f);
    }
}

// ---------------------------------------------------------------------------
// prep kernel 3: pack modulated input (fp16) + padding ring (fused)
// ---------------------------------------------------------------------------
__global__ void k_pack_x(const float* __restrict__ x) {
    const int b = blockIdx.z, hp = blockIdx.y, cin0 = blockIdx.x * 32;
    const int t = threadIdx.x;
    const __half zz = __float2half(0.f);

    if (hp == 0 || hp == 65) {
        for (int idx = t; idx < 66 * 32; idx += 256) {
            const int pw = idx >> 5, c = idx & 31;
            g_x[((size_t)b * NPIX + hp * PADW + pw) * CIN + cin0 + c] = zz;
        }
        return;
    }
    const int h = hp - 1;
    __shared__ float tile[32][65];
    {
        const int w = t & 63, i0 = t >> 6;
#pragma unroll
        for (int j = 0; j < 8; j++) {
            const int ci = i0 * 8 + j;
            tile[ci][w] = x[(((size_t)b * CIN + cin0 + ci) * RES + h) * RES + w];
        }
    }
    if (t < 64) {
        const int c = t & 31, pw = (t < 32) ? 0 : 65;
        g_x[((size_t)b * NPIX + hp * PADW + pw) * CIN + cin0 + c] = zz;
    }
    __syncthreads();
    {
        const int c = t & 31, w0 = t >> 5;
        const float st = g_styles[b * CIN + cin0 + c];
        for (int w = w0; w < 64; w += 8) {
            g_x[((size_t)b * NPIX + hp * PADW + (w + 1)) * CIN + cin0 + c] =
                __float2half(tile[c][w] * st);
        }
    }
}

// ---------------------------------------------------------------------------
// main conv kernel: mma.sync fp16 implicit GEMM (2-combo: w split, x single)
// CTA: M=128 couts x N=256 pixels, 256 threads / 8 warps, warp tile 64x64
// K-loop: 72 iters, 2-stage cp.async pipeline, 1 sync/iter
// ---------------------------------------------------------------------------
#define OFF_AH  0
#define OFF_AL  16384
#define OFF_B   32768
#define STAGE   65536
#define SMEM_DYN (2 * STAGE)

extern __shared__ __align__(1024) char smem[];

__global__ void __launch_bounds__(256, 1)
k_conv(const float* __restrict__ bias,
       const float* __restrict__ noise_const,
       const float* __restrict__ noise_strength,
       float* __restrict__ out) {
    const int tid   = threadIdx.x;
    const int wid   = tid >> 5;
    const int lid   = tid & 31;
    const int ptile = blockIdx.x;            // 0..15 (256 pixels = 4 rows each)
    const int cout0 = blockIdx.y * 128;      // 0..3
    const int b     = blockIdx.z;
    const int wm    = wid >> 2;              // 0..1 (M warp: 64 rows)
    const int wn    = wid & 3;               // 0..3 (N warp: 64 pixels)

    const uint32_t sb = smem_u32(smem);

    // ---- loader invariants: A row (hi/lo by tid>>7) + B row (tid)
    const int arow_l = tid & 127;
    const uint32_t aoffP = (tid < 128) ? OFF_AH : OFF_AL;
    const __half* aplane = (tid < 128) ? g_ah : g_al;
    const size_t arow = (size_t)(cout0 + arow_l) * CIN;

    const int gp = ptile * 256 + tid;
    const size_t browoff = ((size_t)b * NPIX + (gp >> 6) * PADW + (gp & 63)) * CIN;

    // ---- ldmatrix per-lane base offsets
    uint32_t aoff[4], boff[4];
#pragma unroll
    for (int mt = 0; mt < 4; mt++)
        aoff[mt] = (uint32_t)((wm * 64 + mt * 16 + (lid & 15)) << 7) + ((lid >> 4) << 4);
#pragma unroll
    for (int p = 0; p < 4; p++)
        boff[p] = (uint32_t)((wn * 64 + p * 16 + ((lid >> 4) & 1) * 8 + (lid & 7)) << 7)
                + (((lid >> 3) & 1) << 4);

    float acc[4][8][4];
#pragma unroll
    for (int mt = 0; mt < 4; mt++)
#pragma unroll
        for (int nt = 0; nt < 8; nt++)
#pragma unroll
            for (int i = 0; i < 4; i++) acc[mt][nt][i] = 0.f;

    // ---- stage loader (slot = it & 1): 16 cp.async per thread
    auto load_stage = [&](int it) {
        const int tap = it >> 3, cin0 = (it & 7) << 6;
        const int dh = tap / 3, dw = tap - dh * 3;
        const uint32_t stg = sb + (uint32_t)(it & 1) * STAGE;
        const char* asrc = (const char*)(aplane + ((size_t)tap * COUT * CIN + arow + cin0));
        const char* bsrc = (const char*)(g_x + (browoff + (size_t)(dh * PADW + dw) * CIN + cin0));
        const uint32_t da = stg + aoffP, db = stg + OFF_B;
#pragma unroll
        for (int sg = 0; sg < 8; sg++) {
            cpa16(da + sw128((uint32_t)(arow_l * 128 + sg * 16)), asrc + sg * 16);
            cpa16(db + sw128((uint32_t)(tid * 128 + sg * 16)),    bsrc + sg * 16);
        }
        CP_COMMIT();
    };

    load_stage(0);

#pragma unroll 1
    for (int it = 0; it < 72; it++) {
        CP_WAIT0();            // slot it&1 ready
        __syncthreads();       // everyone done reading slot (it+1)&1
        if (it + 1 < 72) load_stage(it + 1);

        const uint32_t stgA = sb + (uint32_t)(it & 1) * STAGE;
        const uint32_t stgB = stgA + OFF_B;

#pragma unroll
        for (int kk = 0; kk < 4; kk++) {
            uint32_t ah[4][4], al[4][4], bf[4][4];
#pragma unroll
            for (int mt = 0; mt < 4; mt++) {
                const uint32_t ad = stgA + sw128(aoff[mt] + kk * 32);
                ldsm4(ah[mt], ad);
                ldsm4(al[mt], ad + 16384);
            }
#pragma unroll
            for (int p = 0; p < 4; p++)
                ldsm4(bf[p], stgB + sw128(boff[p] + kk * 32));

            // combo-major: acc reuse distance 32 MMAs
#pragma unroll
            for (int p = 0; p < 4; p++)
#pragma unroll
                for (int h2 = 0; h2 < 2; h2++)
#pragma unroll
                    for (int mt = 0; mt < 4; mt++)
                        mma_f16(acc[mt][p * 2 + h2], ah[mt], &bf[p][h2 * 2]);
#pragma unroll
            for (int p = 0; p < 4; p++)
#pragma unroll
                for (int h2 = 0; h2 < 2; h2++)
#pragma unroll
                    for (int mt = 0; mt < 4; mt++)
                        mma_f16(acc[mt][p * 2 + h2], al[mt], &bf[p][h2 * 2]);
        }
    }

    // ---- epilogue: demodulate, noise, bias, lrelu*sqrt(2), float2 stores
    const int g = lid >> 2, t2 = (lid & 3) * 2;
    const float ns = noise_strength[0];
    float nz[8][2];
    int hh[8], ww[8];
#pragma unroll
    for (int nt = 0; nt < 8; nt++) {
        const int n = ptile * 256 + wn * 64 + nt * 8 + t2;
        hh[nt] = n >> 6; ww[nt] = n & 63;
        nz[nt][0] = noise_const[hh[nt] * RES + ww[nt]] * ns;
        nz[nt][1] = noise_const[hh[nt] * RES + ww[nt] + 1] * ns;
    }
#pragma unroll
    for (int mt = 0; mt < 4; mt++) {
#pragma unroll
        for (int rr = 0; rr < 2; rr++) {
            const int co = cout0 + wm * 64 + mt * 16 + g + rr * 8;
            const float dc = g_dcoefs[b * COUT + co];
            const float bi = bias[co];
#pragma unroll
            for (int nt = 0; nt < 8; nt++) {
                float v0 = acc[mt][nt][rr * 2 + 0] * dc + nz[nt][0] + bi;
                float v1 = acc[mt][nt][rr * 2 + 1] * dc + nz[nt][1] + bi;
                v0 = (v0 > 0.f ? v0 : 0.2f * v0) * 1.4142135623730951f;
                v1 = (v1 > 0.f ? v1 : 0.2f * v1) * 1.4142135623730951f;
                float2* o = (float2*)&out[(((size_t)b * COUT + co) * RES + hh[nt]) * RES + ww[nt]];
                *o = make_float2(v0, v1);
            }
        }
    }
}

// ---------------------------------------------------------------------------
// launch: 4 kernels (ncu -s 5 lands on k_conv)
// ---------------------------------------------------------------------------
extern "C" void kernel_launch(void* const* d_in, const int* in_sizes, int n_in,
                              void* d_out, int out_size) {
    (void)in_sizes; (void)n_in; (void)out_size;
    const float* x              = (const float*)d_in[0];
    const float* w              = (const float*)d_in[1];
    const float* affine_w       = (const float*)d_in[2];
    const float* affine_b       = (const float*)d_in[3];
    const float* weight         = (const float*)d_in[4];
    const float* bias           = (const float*)d_in[5];
    const float* noise_const    = (const float*)d_in[6];
    const float* noise_strength = (const float*)d_in[7];
    float* out = (float*)d_out;

    cudaFuncSetAttribute(k_conv, cudaFuncAttributeMaxDynamicSharedMemorySize, SMEM_DYN);

    k_styles<<<BB, 512>>>(w, affine_w, affine_b);
    k_prep<<<COUT, 512>>>(weight);
    k_pack_x<<<dim3(16, 66, BB), 256>>>(x);

    dim3 grid(16, COUT / 128, BB);
    k_conv<<<grid, 256, SMEM_DYN>>>(bias, noise_const, noise_strength, out);
}

// round 9
// speedup vs baseline: 1.7804x; 1.0811x over previous
#include <cuda_runtime.h>
#include <cuda_fp16.h>
#include <cstdint>

#define BB    16
#define CIN   512
#define COUT  512
#define RES   64
#define WDIM  512
#define PADW  66
#define NPIX  (PADW * PADW)

// ---------------------------------------------------------------------------
// device scratch (static globals — no allocations allowed)
// ---------------------------------------------------------------------------
__device__ float g_styles[BB * CIN];
__device__ float g_dcoefs[BB * COUT];
// packed weights: [tap][cout][cin], single fp16 plane
__device__ __align__(1024) __half g_a[9ull * COUT * CIN];
// packed modulated input: [b][padded pixel][cin], single fp16 plane
__device__ __align__(1024) __half g_x[(size_t)BB * NPIX * CIN];

// ---------------------------------------------------------------------------
// PTX helpers (baseline compute_103-safe)
// ---------------------------------------------------------------------------
__device__ __forceinline__ uint32_t smem_u32(const void* p) {
    uint32_t a;
    asm("{ .reg .u64 t; cvta.to.shared.u64 t, %1; cvt.u32.u64 %0, t; }" : "=r"(a) : "l"(p));
    return a;
}
__device__ __forceinline__ void cpa16(uint32_t dst, const void* src) {
    asm volatile("cp.async.cg.shared.global [%0], [%1], 16;" :: "r"(dst), "l"(src));
}
#define CP_COMMIT()  asm volatile("cp.async.commit_group;" ::: "memory")
#define CP_WAIT1()   asm volatile("cp.async.wait_group 1;" ::: "memory")
#define CP_WAIT0()   asm volatile("cp.async.wait_group 0;" ::: "memory")

__device__ __forceinline__ void ldsm4(uint32_t* r, uint32_t a) {
    asm volatile("ldmatrix.sync.aligned.m8n8.x4.shared.b16 {%0,%1,%2,%3}, [%4];"
        : "=r"(r[0]), "=r"(r[1]), "=r"(r[2]), "=r"(r[3]) : "r"(a));
}
__device__ __forceinline__ void mma_f16(float* c, const uint32_t* a, const uint32_t* b) {
    asm volatile("mma.sync.aligned.m16n8k16.row.col.f32.f16.f16.f32 "
        "{%0,%1,%2,%3}, {%4,%5,%6,%7}, {%8,%9}, {%0,%1,%2,%3};"
        : "+f"(c[0]), "+f"(c[1]), "+f"(c[2]), "+f"(c[3])
        : "r"(a[0]), "r"(a[1]), "r"(a[2]), "r"(a[3]), "r"(b[0]), "r"(b[1]));
}
__device__ __forceinline__ uint32_t sw128(uint32_t off) {
    return off ^ ((off >> 3) & 0x70);
}

// ---------------------------------------------------------------------------
// prep kernel 1: styles
// ---------------------------------------------------------------------------
__global__ void k_styles(const float* __restrict__ w,
                         const float* __restrict__ affine_w,
                         const float* __restrict__ affine_b) {
    const int b = blockIdx.x, t = threadIdx.x;
    __shared__ float sw[WDIM];
    sw[t] = w[b * WDIM + t];
    __syncthreads();
    const float gain = 1.0f / sqrtf((float)WDIM);
    float m[3];
#pragma unroll
    for (int j0 = 0; j0 < 3; j0++) {
        const int j = j0 * CIN + t;
        const float* __restrict__ row = affine_w + (size_t)j * WDIM;
        float acc = 0.f;
        for (int k = 0; k < WDIM; k++) acc += row[k] * sw[k];
        m[j0] = acc * gain + affine_b[j];
    }
    g_styles[b * CIN + t] = m[0] * m[1] + m[2];
}

// ---------------------------------------------------------------------------
// prep kernel 2 (fused): pack weights fp16 + wsq + dcoefs
// ---------------------------------------------------------------------------
__global__ void k_prep(const float* __restrict__ weight) {
    const int co = blockIdx.x, ci = threadIdx.x;
    const float* __restrict__ wp = weight + ((size_t)co * CIN + ci) * 9;
    float s = 0.f;
#pragma unroll
    for (int t = 0; t < 9; t++) {
        const float v = wp[t];
        s += v * v;
        g_a[((size_t)t * COUT + co) * CIN + ci] = __float2half(v);
    }
    float p[BB];
#pragma unroll
    for (int b = 0; b < BB; b++) {
        const float st = g_styles[b * CIN + ci];
        p[b] = st * st * s;
    }
#pragma unroll
    for (int b = 0; b < BB; b++)
#pragma unroll
        for (int off = 16; off > 0; off >>= 1)
            p[b] += __shfl_xor_sync(0xFFFFFFFFu, p[b], off);
    __shared__ float red[BB][17];
    const int wrp = ci >> 5, lane = ci & 31;
    if (lane == 0)
#pragma unroll
        for (int b = 0; b < BB; b++) red[b][wrp] = p[b];
    __syncthreads();
    if (ci < BB) {
        float acc = 0.f;
#pragma unroll
        for (int k = 0; k < 16; k++) acc += red[ci][k];
        g_dcoefs[ci * COUT + co] = rsqrtf(acc + 1e-8f);
    }
}

// ---------------------------------------------------------------------------
// prep kernel 3: pack modulated input (fp16) + padding ring (fused)
// ---------------------------------------------------------------------------
__global__ void k_pack_x(const float* __restrict__ x) {
    const int b = blockIdx.z, hp = blockIdx.y, cin0 = blockIdx.x * 32;
    const int t = threadIdx.x;
    const __half zz = __float2half(0.f);

    if (hp == 0 || hp == 65) {
        for (int idx = t; idx < 66 * 32; idx += 256) {
            const int pw = idx >> 5, c = idx & 31;
            g_x[((size_t)b * NPIX + hp * PADW + pw) * CIN + cin0 + c] = zz;
        }
        return;
    }
    const int h = hp - 1;
    __shared__ float tile[32][65];
    {
        const int w = t & 63, i0 = t >> 6;
#pragma unroll
        for (int j = 0; j < 8; j++) {
            const int ci = i0 * 8 + j;
            tile[ci][w] = x[(((size_t)b * CIN + cin0 + ci) * RES + h) * RES + w];
        }
    }
    if (t < 64) {
        const int c = t & 31, pw = (t < 32) ? 0 : 65;
        g_x[((size_t)b * NPIX + hp * PADW + pw) * CIN + cin0 + c] = zz;
    }
    __syncthreads();
    {
        const int c = t & 31, w0 = t >> 5;
        const float st = g_styles[b * CIN + cin0 + c];
        for (int w = w0; w < 64; w += 8) {
            g_x[((size_t)b * NPIX + hp * PADW + (w + 1)) * CIN + cin0 + c] =
                __float2half(tile[c][w] * st);
        }
    }
}

// ---------------------------------------------------------------------------
// main conv kernel: mma.sync fp16 implicit GEMM (single plane)
// CTA: M=128 couts x N=256 pixels, 256 threads / 8 warps, warp tile 64x64
// K-loop: 72 iters, 2-stage cp.async pipeline, 1 sync/iter
// ---------------------------------------------------------------------------
#define OFF_A   0
#define OFF_B   16384
#define STAGE   49152
#define SMEM_DYN (2 * STAGE)

extern __shared__ __align__(1024) char smem[];

__global__ void __launch_bounds__(256, 1)
k_conv(const float* __restrict__ bias,
       const float* __restrict__ noise_const,
       const float* __restrict__ noise_strength,
       float* __restrict__ out) {
    const int tid   = threadIdx.x;
    const int wid   = tid >> 5;
    const int lid   = tid & 31;
    const int ptile = blockIdx.x;            // 0..15 (256 pixels = 4 rows each)
    const int cout0 = blockIdx.y * 128;      // 0..3
    const int b     = blockIdx.z;
    const int wm    = wid >> 2;              // 0..1 (M warp: 64 rows)
    const int wn    = wid & 3;               // 0..3 (N warp: 64 pixels)

    const uint32_t sb = smem_u32(smem);

    // ---- loader invariants: tid<128 loads A row tid; all 256 load B row tid
    const int arow_l = tid & 127;
    const size_t arow = (size_t)(cout0 + arow_l) * CIN;

    const int gp = ptile * 256 + tid;
    const size_t browoff = ((size_t)b * NPIX + (gp >> 6) * PADW + (gp & 63)) * CIN;

    // ---- ldmatrix per-lane base offsets
    uint32_t aoff[4], boff[4];
#pragma unroll
    for (int mt = 0; mt < 4; mt++)
        aoff[mt] = (uint32_t)((wm * 64 + mt * 16 + (lid & 15)) << 7) + ((lid >> 4) << 4);
#pragma unroll
    for (int p = 0; p < 4; p++)
        boff[p] = (uint32_t)((wn * 64 + p * 16 + ((lid >> 4) & 1) * 8 + (lid & 7)) << 7)
                + (((lid >> 3) & 1) << 4);

    float acc[4][8][4];
#pragma unroll
    for (int mt = 0; mt < 4; mt++)
#pragma unroll
        for (int nt = 0; nt < 8; nt++)
#pragma unroll
            for (int i = 0; i < 4; i++) acc[mt][nt][i] = 0.f;

    // ---- stage loader (slot = it & 1): A 8 cp (tid<128) + B 8 cp (all)
    auto load_stage = [&](int it) {
        const int tap = it >> 3, cin0 = (it & 7) << 6;
        const int dh = tap / 3, dw = tap - dh * 3;
        const uint32_t stg = sb + (uint32_t)(it & 1) * STAGE;
        const char* bsrc = (const char*)(g_x + (browoff + (size_t)(dh * PADW + dw) * CIN + cin0));
        const uint32_t db = stg + OFF_B;
#pragma unroll
        for (int sg = 0; sg < 8; sg++)
            cpa16(db + sw128((uint32_t)(tid * 128 + sg * 16)), bsrc + sg * 16);
        if (tid < 128) {
            const char* asrc = (const char*)(g_a + ((size_t)tap * COUT * CIN + arow + cin0));
            const uint32_t da = stg + OFF_A;
#pragma unroll
            for (int sg = 0; sg < 8; sg++)
                cpa16(da + sw128((uint32_t)(arow_l * 128 + sg * 16)), asrc + sg * 16);
        }
        CP_COMMIT();
    };

    load_stage(0);

#pragma unroll 1
    for (int it = 0; it < 72; it++) {
        __syncthreads();                       // compute(it-1) finished -> slot free
        if (it + 1 < 72) { load_stage(it + 1); CP_WAIT1(); }  // issue next, wait cur
        else             { CP_WAIT0(); }
        __syncthreads();                       // slot it&1 visible to all warps

        const uint32_t stgA = sb + (uint32_t)(it & 1) * STAGE;
        const uint32_t stgB = stgA + OFF_B;

#pragma unroll
        for (int kk = 0; kk < 4; kk++) {
            uint32_t af[4][4], bf[4][4];
#pragma unroll
            for (int mt = 0; mt < 4; mt++)
                ldsm4(af[mt], stgA + sw128(aoff[mt] + kk * 32));
#pragma unroll
            for (int p = 0; p < 4; p++)
                ldsm4(bf[p], stgB + sw128(boff[p] + kk * 32));
#pragma unroll
            for (int p = 0; p < 4; p++)
#pragma unroll
                for (int h2 = 0; h2 < 2; h2++)
#pragma unroll
                    for (int mt = 0; mt < 4; mt++)
                        mma_f16(acc[mt][p * 2 + h2], af[mt], &bf[p][h2 * 2]);
        }
    }

    // ---- epilogue: demodulate, noise, bias, lrelu*sqrt(2), float2 stores
    const int g = lid >> 2, t2 = (lid & 3) * 2;
    const float ns = noise_strength[0];
    float nz[8][2];
    int hh[8], ww[8];
#pragma unroll
    for (int nt = 0; nt < 8; nt++) {
        const int n = ptile * 256 + wn * 64 + nt * 8 + t2;
        hh[nt] = n >> 6; ww[nt] = n & 63;
        nz[nt][0] = noise_const[hh[nt] * RES + ww[nt]] * ns;
        nz[nt][1] = noise_const[hh[nt] * RES + ww[nt] + 1] * ns;
    }
#pragma unroll
    for (int mt = 0; mt < 4; mt++) {
#pragma unroll
        for (int rr = 0; rr < 2; rr++) {
            const int co = cout0 + wm * 64 + mt * 16 + g + rr * 8;
            const float dc = g_dcoefs[b * COUT + co];
            const float bi = bias[co];
#pragma unroll
            for (int nt = 0; nt < 8; nt++) {
                float v0 = acc[mt][nt][rr * 2 + 0] * dc + nz[nt][0] + bi;
                float v1 = acc[mt][nt][rr * 2 + 1] * dc + nz[nt][1] + bi;
                v0 = (v0 > 0.f ? v0 : 0.2f * v0) * 1.4142135623730951f;
                v1 = (v1 > 0.f ? v1 : 0.2f * v1) * 1.4142135623730951f;
                float2* o = (float2*)&out[(((size_t)b * COUT + co) * RES + hh[nt]) * RES + ww[nt]];
                *o = make_float2(v0, v1);
            }
        }
    }
}

// ---------------------------------------------------------------------------
// launch: 4 kernels (ncu -s 5 lands on k_conv)
// ---------------------------------------------------------------------------
extern "C" void kernel_launch(void* const* d_in, const int* in_sizes, int n_in,
                              void* d_out, int out_size) {
    (void)in_sizes; (void)n_in; (void)out_size;
    const float* x              = (const float*)d_in[0];
    const float* w              = (const float*)d_in[1];
    const float* affine_w       = (const float*)d_in[2];
    const float* affine_b       = (const float*)d_in[3];
    const float* weight         = (const float*)d_in[4];
    const float* bias           = (const float*)d_in[5];
    const float* noise_const    = (const float*)d_in[6];
    const float* noise_strength = (const float*)d_in[7];
    float* out = (float*)d_out;

    cudaFuncSetAttribute(k_conv, cudaFuncAttributeMaxDynamicSharedMemorySize, SMEM_DYN);

    k_styles<<<BB, 512>>>(w, affine_w, affine_b);
    k_prep<<<COUT, 512>>>(weight);
    k_pack_x<<<dim3(16, 66, BB), 256>>>(x);

    dim3 grid(16, COUT / 128, BB);
    k_conv<<<grid, 256, SMEM_DYN>>>(bias, noise_const, noise_strength, out);
}

// round 10
// speedup vs baseline: 2.4469x; 1.3743x over previous
#include <cuda_runtime.h>
#include <cuda_fp16.h>
#include <cstdint>

#define BB    16
#define CIN   512
#define COUT  512
#define RES   64
#define WDIM  512
#define PADW  66
#define NPIX  (PADW * PADW)

// ---------------------------------------------------------------------------
// device scratch (static globals — no allocations allowed)
// ---------------------------------------------------------------------------
__device__ float g_styles[BB * CIN];
__device__ float g_dcoefs[BB * COUT];
__device__ __align__(1024) __half g_a[9ull * COUT * CIN];          // [tap][cout][cin]
__device__ __align__(1024) __half g_x[(size_t)BB * NPIX * CIN];    // [b][pixel][cin]

// ---------------------------------------------------------------------------
// PTX helpers (baseline compute_103-safe)
// ---------------------------------------------------------------------------
__device__ __forceinline__ uint32_t smem_u32(const void* p) {
    uint32_t a;
    asm("{ .reg .u64 t; cvta.to.shared.u64 t, %1; cvt.u32.u64 %0, t; }" : "=r"(a) : "l"(p));
    return a;
}
__device__ __forceinline__ void cpa16(uint32_t dst, const void* src) {
    asm volatile("cp.async.cg.shared.global [%0], [%1], 16;" :: "r"(dst), "l"(src));
}
#define CP_COMMIT()  asm volatile("cp.async.commit_group;" ::: "memory")
#define CP_WAIT1()   asm volatile("cp.async.wait_group 1;" ::: "memory")
#define CP_WAIT0()   asm volatile("cp.async.wait_group 0;" ::: "memory")

__device__ __forceinline__ void ldsm4(uint32_t* r, uint32_t a) {
    asm volatile("ldmatrix.sync.aligned.m8n8.x4.shared.b16 {%0,%1,%2,%3}, [%4];"
        : "=r"(r[0]), "=r"(r[1]), "=r"(r[2]), "=r"(r[3]) : "r"(a));
}
__device__ __forceinline__ void mma_f16(float* c, const uint32_t* a, const uint32_t* b) {
    asm volatile("mma.sync.aligned.m16n8k16.row.col.f32.f16.f16.f32 "
        "{%0,%1,%2,%3}, {%4,%5,%6,%7}, {%8,%9}, {%0,%1,%2,%3};"
        : "+f"(c[0]), "+f"(c[1]), "+f"(c[2]), "+f"(c[3])
        : "r"(a[0]), "r"(a[1]), "r"(a[2]), "r"(a[3]), "r"(b[0]), "r"(b[1]));
}
__device__ __forceinline__ uint32_t sw128(uint32_t off) {
    return off ^ ((off >> 3) & 0x70);
}

// ---------------------------------------------------------------------------
// prep kernel 1: styles — grid (BB, 3), one output per thread
// ---------------------------------------------------------------------------
__global__ void k_styles(const float* __restrict__ w,
                         const float* __restrict__ affine_w,
                         const float* __restrict__ affine_b,
                         float* __restrict__ proj) {
    const int b = blockIdx.x, j0 = blockIdx.y, t = threadIdx.x;
    __shared__ float sw[WDIM];
    sw[t] = w[b * WDIM + t];
    __syncthreads();
    const float gain = 1.0f / sqrtf((float)WDIM);
    const int j = j0 * CIN + t;
    const float* __restrict__ row = affine_w + (size_t)j * WDIM;
    float acc = 0.f;
#pragma unroll 8
    for (int k = 0; k < WDIM; k++) acc += row[k] * sw[k];
    proj[(b * 3 + j0) * CIN + t] = acc * gain + affine_b[j];
}

__global__ void k_styles2(const float* __restrict__ proj) {
    const int b = blockIdx.x, t = threadIdx.x;
    const float m1 = proj[(b * 3 + 0) * CIN + t];
    const float m2 = proj[(b * 3 + 1) * CIN + t];
    const float m3 = proj[(b * 3 + 2) * CIN + t];
    g_styles[b * CIN + t] = m1 * m2 + m3;
}
__device__ float g_proj[BB * 3 * CIN];

// ---------------------------------------------------------------------------
// prep kernel 2 (fused): pack weights fp16 + wsq + dcoefs
// ---------------------------------------------------------------------------
__global__ void k_prep(const float* __restrict__ weight) {
    const int co = blockIdx.x, ci = threadIdx.x;
    const float* __restrict__ wp = weight + ((size_t)co * CIN + ci) * 9;
    float s = 0.f;
#pragma unroll
    for (int t = 0; t < 9; t++) {
        const float v = wp[t];
        s += v * v;
        g_a[((size_t)t * COUT + co) * CIN + ci] = __float2half(v);
    }
    float p[BB];
#pragma unroll
    for (int b = 0; b < BB; b++) {
        const float st = g_styles[b * CIN + ci];
        p[b] = st * st * s;
    }
#pragma unroll
    for (int b = 0; b < BB; b++)
#pragma unroll
        for (int off = 16; off > 0; off >>= 1)
            p[b] += __shfl_xor_sync(0xFFFFFFFFu, p[b], off);
    __shared__ float red[BB][17];
    const int wrp = ci >> 5, lane = ci & 31;
    if (lane == 0)
#pragma unroll
        for (int b = 0; b < BB; b++) red[b][wrp] = p[b];
    __syncthreads();
    if (ci < BB) {
        float acc = 0.f;
#pragma unroll
        for (int k = 0; k < 16; k++) acc += red[ci][k];
        g_dcoefs[ci * COUT + co] = rsqrtf(acc + 1e-8f);
    }
}

// ---------------------------------------------------------------------------
// prep kernel 3: pack modulated input (fp16) + padding ring (fused)
// ---------------------------------------------------------------------------
__global__ void k_pack_x(const float* __restrict__ x) {
    const int b = blockIdx.z, hp = blockIdx.y, cin0 = blockIdx.x * 32;
    const int t = threadIdx.x;
    const __half zz = __float2half(0.f);

    if (hp == 0 || hp == 65) {
        for (int idx = t; idx < 66 * 32; idx += 256) {
            const int pw = idx >> 5, c = idx & 31;
            g_x[((size_t)b * NPIX + hp * PADW + pw) * CIN + cin0 + c] = zz;
        }
        return;
    }
    const int h = hp - 1;
    __shared__ float tile[32][65];
    {
        const int w = t & 63, i0 = t >> 6;
#pragma unroll
        for (int j = 0; j < 8; j++) {
            const int ci = i0 * 8 + j;
            tile[ci][w] = x[(((size_t)b * CIN + cin0 + ci) * RES + h) * RES + w];
        }
    }
    if (t < 64) {
        const int c = t & 31, pw = (t < 32) ? 0 : 65;
        g_x[((size_t)b * NPIX + hp * PADW + pw) * CIN + cin0 + c] = zz;
    }
    __syncthreads();
    {
        const int c = t & 31, w0 = t >> 5;
        const float st = g_styles[b * CIN + cin0 + c];
        for (int w = w0; w < 64; w += 8) {
            g_x[((size_t)b * NPIX + hp * PADW + (w + 1)) * CIN + cin0 + c] =
                __float2half(tile[c][w] * st);
        }
    }
}

// ---------------------------------------------------------------------------
// main conv kernel: mma.sync fp16 implicit GEMM (single plane)
// CTA: M=128 x N=128, 256 threads / 8 warps, warp tile 64x32, 2 CTAs/SM
// K-loop: 72 iters, 2-stage cp.async pipeline
// ---------------------------------------------------------------------------
#define OFF_A   0
#define OFF_B   16384
#define STAGE   32768
#define SMEM_DYN (2 * STAGE)

extern __shared__ __align__(1024) char smem[];

__global__ void __launch_bounds__(256, 2)
k_conv(const float* __restrict__ bias,
       const float* __restrict__ noise_const,
       const float* __restrict__ noise_strength,
       float* __restrict__ out) {
    const int tid   = threadIdx.x;
    const int wid   = tid >> 5;
    const int lid   = tid & 31;
    const int ptile = blockIdx.x;            // 0..31 (128 pixels = 2 rows each)
    const int cout0 = blockIdx.y * 128;      // 0..3
    const int b     = blockIdx.z;
    const int wm    = wid >> 2;              // 0..1 (M warp: 64 rows)
    const int wn    = wid & 3;               // 0..3 (N warp: 32 pixels)

    const uint32_t sb = smem_u32(smem);

    // ---- loader invariants: tid<128 -> A row tid; tid>=128 -> B row tid-128
    const int rowid = tid & 127;
    const bool isA  = (tid < 128);
    const size_t arow = (size_t)(cout0 + rowid) * CIN;
    const int gp = ptile * 128 + rowid;
    const size_t browoff = ((size_t)b * NPIX + (gp >> 6) * PADW + (gp & 63)) * CIN;
    const uint32_t doff = isA ? OFF_A : OFF_B;

    uint32_t swr[8];
#pragma unroll
    for (int sg = 0; sg < 8; sg++) swr[sg] = sw128((uint32_t)(rowid * 128 + sg * 16));

    // ---- ldmatrix per-lane base offsets
    uint32_t aoff[4], boff[2];
#pragma unroll
    for (int mt = 0; mt < 4; mt++)
        aoff[mt] = (uint32_t)((wm * 64 + mt * 16 + (lid & 15)) << 7) + ((lid >> 4) << 4);
#pragma unroll
    for (int p = 0; p < 2; p++)
        boff[p] = (uint32_t)((wn * 32 + p * 16 + ((lid >> 4) & 1) * 8 + (lid & 7)) << 7)
                + (((lid >> 3) & 1) << 4);

    float acc[4][4][4];
#pragma unroll
    for (int mt = 0; mt < 4; mt++)
#pragma unroll
        for (int nt = 0; nt < 4; nt++)
#pragma unroll
            for (int i = 0; i < 4; i++) acc[mt][nt][i] = 0.f;

    // ---- stage loader (slot = it & 1): 8 cp.async per thread
    auto load_stage = [&](int it) {
        const int tap = it >> 3, cin0 = (it & 7) << 6;
        const int dh = tap / 3, dw = tap - dh * 3;
        const uint32_t stg = sb + (uint32_t)(it & 1) * STAGE;
        const char* src = isA
            ? (const char*)(g_a + ((size_t)tap * COUT * CIN + arow + cin0))
            : (const char*)(g_x + (browoff + (size_t)(dh * PADW + dw) * CIN + cin0));
        const uint32_t dst = stg + doff;
#pragma unroll
        for (int sg = 0; sg < 8; sg++) cpa16(dst + swr[sg], src + sg * 16);
        CP_COMMIT();
    };

    load_stage(0);

#pragma unroll 1
    for (int it = 0; it < 72; it++) {
        __syncthreads();                       // compute(it-1) done -> slot free
        if (it + 1 < 72) { load_stage(it + 1); CP_WAIT1(); }
        else             { CP_WAIT0(); }
        __syncthreads();                       // slot it&1 visible

        const uint32_t stgA = sb + (uint32_t)(it & 1) * STAGE;
        const uint32_t stgB = stgA + OFF_B;

#pragma unroll
        for (int kk = 0; kk < 4; kk++) {
            uint32_t af[4][4], bf[2][4];
#pragma unroll
            for (int mt = 0; mt < 4; mt++)
                ldsm4(af[mt], stgA + sw128(aoff[mt] + kk * 32));
#pragma unroll
            for (int p = 0; p < 2; p++)
                ldsm4(bf[p], stgB + sw128(boff[p] + kk * 32));
#pragma unroll
            for (int p = 0; p < 2; p++)
#pragma unroll
                for (int h2 = 0; h2 < 2; h2++)
#pragma unroll
                    for (int mt = 0; mt < 4; mt++)
                        mma_f16(acc[mt][p * 2 + h2], af[mt], &bf[p][h2 * 2]);
        }
    }

    // ---- epilogue: demodulate, noise, bias, lrelu*sqrt(2), float2 stores
    const int g = lid >> 2, t2 = (lid & 3) * 2;
    const float ns = noise_strength[0];
    float nz[4][2];
    int hh[4], ww[4];
#pragma unroll
    for (int nt = 0; nt < 4; nt++) {
        const int n = ptile * 128 + wn * 32 + nt * 8 + t2;
        hh[nt] = n >> 6; ww[nt] = n & 63;
        nz[nt][0] = noise_const[hh[nt] * RES + ww[nt]] * ns;
        nz[nt][1] = noise_const[hh[nt] * RES + ww[nt] + 1] * ns;
    }
#pragma unroll
    for (int mt = 0; mt < 4; mt++) {
#pragma unroll
        for (int rr = 0; rr < 2; rr++) {
            const int co = cout0 + wm * 64 + mt * 16 + g + rr * 8;
            const float dc = g_dcoefs[b * COUT + co];
            const float bi = bias[co];
#pragma unroll
            for (int nt = 0; nt < 4; nt++) {
                float v0 = acc[mt][nt][rr * 2 + 0] * dc + nz[nt][0] + bi;
                float v1 = acc[mt][nt][rr * 2 + 1] * dc + nz[nt][1] + bi;
                v0 = (v0 > 0.f ? v0 : 0.2f * v0) * 1.4142135623730951f;
                v1 = (v1 > 0.f ? v1 : 0.2f * v1) * 1.4142135623730951f;
                float2* o = (float2*)&out[(((size_t)b * COUT + co) * RES + hh[nt]) * RES + ww[nt]];
                *o = make_float2(v0, v1);
            }
        }
    }
}

// ---------------------------------------------------------------------------
// launch
// ---------------------------------------------------------------------------
extern "C" void kernel_launch(void* const* d_in, const int* in_sizes, int n_in,
                              void* d_out, int out_size) {
    (void)in_sizes; (void)n_in; (void)out_size;
    const float* x              = (const float*)d_in[0];
    const float* w              = (const float*)d_in[1];
    const float* affine_w       = (const float*)d_in[2];
    const float* affine_b       = (const float*)d_in[3];
    const float* weight         = (const float*)d_in[4];
    const float* bias           = (const float*)d_in[5];
    const float* noise_const    = (const float*)d_in[6];
    const float* noise_strength = (const float*)d_in[7];
    float* out = (float*)d_out;

    cudaFuncSetAttribute(k_conv, cudaFuncAttributeMaxDynamicSharedMemorySize, SMEM_DYN);

    float* proj = nullptr;
    cudaGetSymbolAddress((void**)&proj, g_proj);

    k_styles<<<dim3(BB, 3), 512>>>(w, affine_w, affine_b, proj);
    k_styles2<<<BB, 512>>>(proj);
    k_prep<<<COUT, 512>>>(weight);
    k_pack_x<<<dim3(16, 66, BB), 256>>>(x);

    dim3 grid(32, COUT / 128, BB);
    k_conv<<<grid, 256, SMEM_DYN>>>(bias, noise_const, noise_strength, out);
}

// round 11
// speedup vs baseline: 2.6297x; 1.0747x over previous
#include <cuda_runtime.h>
#include <cuda_fp16.h>
#include <cstdint>

#define BB    16
#define CIN   512
#define COUT  512
#define RES   64
#define WDIM  512
#define PADW  66
#define NPIX  (PADW * PADW)

// ---------------------------------------------------------------------------
// device scratch (static globals — no allocations allowed)
// ---------------------------------------------------------------------------
__device__ float g_proj[BB * 3 * CIN];
__device__ float g_styles[BB * CIN];
__device__ float g_dcoefs[BB * COUT];
__device__ __align__(1024) __half g_a[9ull * COUT * CIN];          // [tap][cout][cin]
__device__ __align__(1024) __half g_x[(size_t)BB * NPIX * CIN];    // [b][pixel][cin]

// ---------------------------------------------------------------------------
// PTX helpers (baseline compute_103-safe)
// ---------------------------------------------------------------------------
__device__ __forceinline__ uint32_t smem_u32(const void* p) {
    uint32_t a;
    asm("{ .reg .u64 t; cvta.to.shared.u64 t, %1; cvt.u32.u64 %0, t; }" : "=r"(a) : "l"(p));
    return a;
}
__device__ __forceinline__ void cpa16(uint32_t dst, const void* src) {
    asm volatile("cp.async.cg.shared.global [%0], [%1], 16;" :: "r"(dst), "l"(src));
}
#define CP_COMMIT()  asm volatile("cp.async.commit_group;" ::: "memory")
#define CP_WAIT1()   asm volatile("cp.async.wait_group 1;" ::: "memory")
#define CP_WAIT0()   asm volatile("cp.async.wait_group 0;" ::: "memory")

__device__ __forceinline__ void ldsm4(uint32_t* r, uint32_t a) {
    asm volatile("ldmatrix.sync.aligned.m8n8.x4.shared.b16 {%0,%1,%2,%3}, [%4];"
        : "=r"(r[0]), "=r"(r[1]), "=r"(r[2]), "=r"(r[3]) : "r"(a));
}
__device__ __forceinline__ void mma_f16(float* c, const uint32_t* a, const uint32_t* b) {
    asm volatile("mma.sync.aligned.m16n8k16.row.col.f32.f16.f16.f32 "
        "{%0,%1,%2,%3}, {%4,%5,%6,%7}, {%8,%9}, {%0,%1,%2,%3};"
        : "+f"(c[0]), "+f"(c[1]), "+f"(c[2]), "+f"(c[3])
        : "r"(a[0]), "r"(a[1]), "r"(a[2]), "r"(a[3]), "r"(b[0]), "r"(b[1]));
}
__device__ __forceinline__ uint32_t sw128(uint32_t off) {
    return off ^ ((off >> 3) & 0x70);
}

// ---------------------------------------------------------------------------
// prep kernel 1: coalesced styles GEMV
// grid = 192 blocks x 256 threads (8 warps). warp j = blockIdx*8 + wid owns
// affine_w row j; lanes stride k coalesced; 16 batch accumulators; butterfly.
// ---------------------------------------------------------------------------
__global__ void k_styles(const float* __restrict__ w,
                         const float* __restrict__ affine_w,
                         const float* __restrict__ affine_b) {
    __shared__ float sw[BB][WDIM];
    const int tid = threadIdx.x;
    for (int i = tid; i < BB * WDIM; i += 256)
        ((float*)sw)[i] = w[i];                 // w is [BB][WDIM] contiguous
    __syncthreads();

    const int wid = tid >> 5, lid = tid & 31;
    const int j = blockIdx.x * 8 + wid;         // 0..1535
    const float* __restrict__ row = affine_w + (size_t)j * WDIM;

    float acc[BB];
#pragma unroll
    for (int b = 0; b < BB; b++) acc[b] = 0.f;
#pragma unroll 4
    for (int k = lid; k < WDIM; k += 32) {
        const float rv = row[k];
#pragma unroll
        for (int b = 0; b < BB; b++) acc[b] += rv * sw[b][k];
    }
#pragma unroll
    for (int b = 0; b < BB; b++)
#pragma unroll
        for (int off = 16; off > 0; off >>= 1)
            acc[b] += __shfl_xor_sync(0xFFFFFFFFu, acc[b], off);

    if (lid < BB) {
        const float gain = 1.0f / sqrtf((float)WDIM);
        g_proj[lid * 3 * CIN + j] = acc[lid] * gain + affine_b[j];
    }
}

// ---------------------------------------------------------------------------
// prep kernel 2 (fused): styles = m1*m2+m3, pack weights fp16, wsq, dcoefs
// grid = COUT blocks x 512 threads (one thread per cin)
// ---------------------------------------------------------------------------
__global__ void k_prep(const float* __restrict__ weight) {
    const int co = blockIdx.x, ci = threadIdx.x;

    // styles for this cin, all batches (from proj)
    float st[BB];
#pragma unroll
    for (int b = 0; b < BB; b++) {
        const float m1 = g_proj[b * 3 * CIN + 0 * CIN + ci];
        const float m2 = g_proj[b * 3 * CIN + 1 * CIN + ci];
        const float m3 = g_proj[b * 3 * CIN + 2 * CIN + ci];
        st[b] = m1 * m2 + m3;
    }
    if (co == 0) {   // publish for k_pack_x (launched after k_prep)
#pragma unroll
        for (int b = 0; b < BB; b++) g_styles[b * CIN + ci] = st[b];
    }

    const float* __restrict__ wp = weight + ((size_t)co * CIN + ci) * 9;
    float s = 0.f;
#pragma unroll
    for (int t = 0; t < 9; t++) {
        const float v = wp[t];
        s += v * v;
        g_a[((size_t)t * COUT + co) * CIN + ci] = __float2half(v);
    }
    float p[BB];
#pragma unroll
    for (int b = 0; b < BB; b++) p[b] = st[b] * st[b] * s;
#pragma unroll
    for (int b = 0; b < BB; b++)
#pragma unroll
        for (int off = 16; off > 0; off >>= 1)
            p[b] += __shfl_xor_sync(0xFFFFFFFFu, p[b], off);
    __shared__ float red[BB][17];
    const int wrp = ci >> 5, lane = ci & 31;
    if (lane == 0)
#pragma unroll
        for (int b = 0; b < BB; b++) red[b][wrp] = p[b];
    __syncthreads();
    if (ci < BB) {
        float acc = 0.f;
#pragma unroll
        for (int k = 0; k < 16; k++) acc += red[ci][k];
        g_dcoefs[ci * COUT + co] = rsqrtf(acc + 1e-8f);
    }
}

// ---------------------------------------------------------------------------
// prep kernel 3: pack modulated input (fp16) + padding ring (fused)
// ---------------------------------------------------------------------------
__global__ void k_pack_x(const float* __restrict__ x) {
    const int b = blockIdx.z, hp = blockIdx.y, cin0 = blockIdx.x * 32;
    const int t = threadIdx.x;
    const __half zz = __float2half(0.f);

    if (hp == 0 || hp == 65) {
        for (int idx = t; idx < 66 * 32; idx += 256) {
            const int pw = idx >> 5, c = idx & 31;
            g_x[((size_t)b * NPIX + hp * PADW + pw) * CIN + cin0 + c] = zz;
        }
        return;
    }
    const int h = hp - 1;
    __shared__ float tile[32][65];
    {
        const int w = t & 63, i0 = t >> 6;
#pragma unroll
        for (int j = 0; j < 8; j++) {
            const int ci = i0 * 8 + j;
            tile[ci][w] = x[(((size_t)b * CIN + cin0 + ci) * RES + h) * RES + w];
        }
    }
    if (t < 64) {
        const int c = t & 31, pw = (t < 32) ? 0 : 65;
        g_x[((size_t)b * NPIX + hp * PADW + pw) * CIN + cin0 + c] = zz;
    }
    __syncthreads();
    {
        const int c = t & 31, w0 = t >> 5;
        const float st = g_styles[b * CIN + cin0 + c];
        for (int w = w0; w < 64; w += 8) {
            g_x[((size_t)b * NPIX + hp * PADW + (w + 1)) * CIN + cin0 + c] =
                __float2half(tile[c][w] * st);
        }
    }
}

// ---------------------------------------------------------------------------
// main conv kernel: mma.sync fp16 implicit GEMM (single plane)
// CTA: M=128 x N=128, 256 threads / 8 warps, warp tile 64x32, 2 CTAs/SM
// K-loop: 72 iters, 2-stage cp.async pipeline
// ---------------------------------------------------------------------------
#define OFF_A   0
#define OFF_B   16384
#define STAGE   32768
#define SMEM_DYN (2 * STAGE)

extern __shared__ __align__(1024) char smem[];

__global__ void __launch_bounds__(256, 2)
k_conv(const float* __restrict__ bias,
       const float* __restrict__ noise_const,
       const float* __restrict__ noise_strength,
       float* __restrict__ out) {
    const int tid   = threadIdx.x;
    const int wid   = tid >> 5;
    const int lid   = tid & 31;
    const int ptile = blockIdx.x;            // 0..31 (128 pixels = 2 rows each)
    const int cout0 = blockIdx.y * 128;      // 0..3
    const int b     = blockIdx.z;
    const int wm    = wid >> 2;              // 0..1 (M warp: 64 rows)
    const int wn    = wid & 3;               // 0..3 (N warp: 32 pixels)

    const uint32_t sb = smem_u32(smem);

    // ---- loader invariants: tid<128 -> A row tid; tid>=128 -> B row tid-128
    const int rowid = tid & 127;
    const bool isA  = (tid < 128);
    const size_t arow = (size_t)(cout0 + rowid) * CIN;
    const int gp = ptile * 128 + rowid;
    const size_t browoff = ((size_t)b * NPIX + (gp >> 6) * PADW + (gp & 63)) * CIN;
    const uint32_t doff = isA ? OFF_A : OFF_B;

    uint32_t swr[8];
#pragma unroll
    for (int sg = 0; sg < 8; sg++) swr[sg] = sw128((uint32_t)(rowid * 128 + sg * 16));

    // ---- ldmatrix per-lane base offsets
    uint32_t aoff[4], boff[2];
#pragma unroll
    for (int mt = 0; mt < 4; mt++)
        aoff[mt] = (uint32_t)((wm * 64 + mt * 16 + (lid & 15)) << 7) + ((lid >> 4) << 4);
#pragma unroll
    for (int p = 0; p < 2; p++)
        boff[p] = (uint32_t)((wn * 32 + p * 16 + ((lid >> 4) & 1) * 8 + (lid & 7)) << 7)
                + (((lid >> 3) & 1) << 4);

    float acc[4][4][4];
#pragma unroll
    for (int mt = 0; mt < 4; mt++)
#pragma unroll
        for (int nt = 0; nt < 4; nt++)
#pragma unroll
            for (int i = 0; i < 4; i++) acc[mt][nt][i] = 0.f;

    // ---- stage loader (slot = it & 1): 8 cp.async per thread
    auto load_stage = [&](int it) {
        const int tap = it >> 3, cin0 = (it & 7) << 6;
        const int dh = tap / 3, dw = tap - dh * 3;
        const uint32_t stg = sb + (uint32_t)(it & 1) * STAGE;
        const char* src = isA
            ? (const char*)(g_a + ((size_t)tap * COUT * CIN + arow + cin0))
            : (const char*)(g_x + (browoff + (size_t)(dh * PADW + dw) * CIN + cin0));
        const uint32_t dst = stg + doff;
#pragma unroll
        for (int sg = 0; sg < 8; sg++) cpa16(dst + swr[sg], src + sg * 16);
        CP_COMMIT();
    };

    load_stage(0);

#pragma unroll 1
    for (int it = 0; it < 72; it++) {
        __syncthreads();                       // compute(it-1) done -> slot free
        if (it + 1 < 72) { load_stage(it + 1); CP_WAIT1(); }
        else             { CP_WAIT0(); }
        __syncthreads();                       // slot it&1 visible

        const uint32_t stgA = sb + (uint32_t)(it & 1) * STAGE;
        const uint32_t stgB = stgA + OFF_B;

#pragma unroll
        for (int kk = 0; kk < 4; kk++) {
            uint32_t af[4][4], bf[2][4];
#pragma unroll
            for (int mt = 0; mt < 4; mt++)
                ldsm4(af[mt], stgA + sw128(aoff[mt] + kk * 32));
#pragma unroll
            for (int p = 0; p < 2; p++)
                ldsm4(bf[p], stgB + sw128(boff[p] + kk * 32));
#pragma unroll
            for (int p = 0; p < 2; p++)
#pragma unroll
                for (int h2 = 0; h2 < 2; h2++)
#pragma unroll
                    for (int mt = 0; mt < 4; mt++)
                        mma_f16(acc[mt][p * 2 + h2], af[mt], &bf[p][h2 * 2]);
        }
    }

    // ---- epilogue: demodulate, noise, bias, lrelu*sqrt(2), float2 stores
    const int g = lid >> 2, t2 = (lid & 3) * 2;
    const float ns = noise_strength[0];
    float nz[4][2];
    int hh[4], ww[4];
#pragma unroll
    for (int nt = 0; nt < 4; nt++) {
        const int n = ptile * 128 + wn * 32 + nt * 8 + t2;
        hh[nt] = n >> 6; ww[nt] = n & 63;
        nz[nt][0] = noise_const[hh[nt] * RES + ww[nt]] * ns;
        nz[nt][1] = noise_const[hh[nt] * RES + ww[nt] + 1] * ns;
    }
#pragma unroll
    for (int mt = 0; mt < 4; mt++) {
#pragma unroll
        for (int rr = 0; rr < 2; rr++) {
            const int co = cout0 + wm * 64 + mt * 16 + g + rr * 8;
            const float dc = g_dcoefs[b * COUT + co];
            const float bi = bias[co];
#pragma unroll
            for (int nt = 0; nt < 4; nt++) {
                float v0 = acc[mt][nt][rr * 2 + 0] * dc + nz[nt][0] + bi;
                float v1 = acc[mt][nt][rr * 2 + 1] * dc + nz[nt][1] + bi;
                v0 = (v0 > 0.f ? v0 : 0.2f * v0) * 1.4142135623730951f;
                v1 = (v1 > 0.f ? v1 : 0.2f * v1) * 1.4142135623730951f;
                float2* o = (float2*)&out[(((size_t)b * COUT + co) * RES + hh[nt]) * RES + ww[nt]];
                *o = make_float2(v0, v1);
            }
        }
    }
}

// ---------------------------------------------------------------------------
// launch: 4 kernels (ncu -s 5 lands on k_conv)
// ---------------------------------------------------------------------------
extern "C" void kernel_launch(void* const* d_in, const int* in_sizes, int n_in,
                              void* d_out, int out_size) {
    (void)in_sizes; (void)n_in; (void)out_size;
    const float* x              = (const float*)d_in[0];
    const float* w              = (const float*)d_in[1];
    const float* affine_w       = (const float*)d_in[2];
    const float* affine_b       = (const float*)d_in[3];
    const float* weight         = (const float*)d_in[4];
    const float* bias           = (const float*)d_in[5];
    const float* noise_const    = (const float*)d_in[6];
    const float* noise_strength = (const float*)d_in[7];
    float* out = (float*)d_out;

    cudaFuncSetAttribute(k_conv, cudaFuncAttributeMaxDynamicSharedMemorySize, SMEM_DYN);

    k_styles<<<192, 256>>>(w, affine_w, affine_b);
    k_prep<<<COUT, 512>>>(weight);
    k_pack_x<<<dim3(16, 66, BB), 256>>>(x);

    dim3 grid(32, COUT / 128, BB);
    k_conv<<<grid, 256, SMEM_DYN>>>(bias, noise_const, noise_strength, out);
}

// round 12
// speedup vs baseline: 3.4632x; 1.3170x over previous
#include <cuda_runtime.h>
#include <cuda_fp16.h>
#include <cstdint>

#define BB    16
#define CIN   512
#define COUT  512
#define RES   64
#define WDIM  512
#define PADW  66
#define NPIX  (PADW * PADW)

// ---------------------------------------------------------------------------
// device scratch (static globals — no allocations allowed)
// ---------------------------------------------------------------------------
__device__ float g_proj[BB * 3 * CIN];
__device__ float g_styles[BB * CIN];
__device__ float g_dcoefs[BB * COUT];
__device__ __align__(1024) __half g_a[9ull * COUT * CIN];          // [tap][cout][cin]
__device__ __align__(1024) __half g_x[(size_t)BB * NPIX * CIN];    // [b][pixel][cin]

// ---------------------------------------------------------------------------
// PTX helpers (baseline compute_103-safe)
// ---------------------------------------------------------------------------
__device__ __forceinline__ uint32_t smem_u32(const void* p) {
    uint32_t a;
    asm("{ .reg .u64 t; cvta.to.shared.u64 t, %1; cvt.u32.u64 %0, t; }" : "=r"(a) : "l"(p));
    return a;
}
__device__ __forceinline__ void cpa16(uint32_t dst, const void* src) {
    asm volatile("cp.async.cg.shared.global [%0], [%1], 16;" :: "r"(dst), "l"(src));
}
#define CP_COMMIT()  asm volatile("cp.async.commit_group;" ::: "memory")
#define CP_WAIT1()   asm volatile("cp.async.wait_group 1;" ::: "memory")
#define CP_WAIT0()   asm volatile("cp.async.wait_group 0;" ::: "memory")

__device__ __forceinline__ void ldsm4(uint32_t* r, uint32_t a) {
    asm volatile("ldmatrix.sync.aligned.m8n8.x4.shared.b16 {%0,%1,%2,%3}, [%4];"
        : "=r"(r[0]), "=r"(r[1]), "=r"(r[2]), "=r"(r[3]) : "r"(a));
}
__device__ __forceinline__ void mma_f16(float* c, const uint32_t* a, const uint32_t* b) {
    asm volatile("mma.sync.aligned.m16n8k16.row.col.f32.f16.f16.f32 "
        "{%0,%1,%2,%3}, {%4,%5,%6,%7}, {%8,%9}, {%0,%1,%2,%3};"
        : "+f"(c[0]), "+f"(c[1]), "+f"(c[2]), "+f"(c[3])
        : "r"(a[0]), "r"(a[1]), "r"(a[2]), "r"(a[3]), "r"(b[0]), "r"(b[1]));
}
__device__ __forceinline__ uint32_t sw128(uint32_t off) {
    return off ^ ((off >> 3) & 0x70);
}

// ---------------------------------------------------------------------------
// prep kernel 1: coalesced styles GEMV (warp per affine_w row)
// ---------------------------------------------------------------------------
__global__ void k_styles(const float* __restrict__ w,
                         const float* __restrict__ affine_w,
                         const float* __restrict__ affine_b) {
    __shared__ float sw[BB][WDIM];
    const int tid = threadIdx.x;
    for (int i = tid; i < BB * WDIM; i += 256)
        ((float*)sw)[i] = w[i];
    __syncthreads();

    const int wid = tid >> 5, lid = tid & 31;
    const int j = blockIdx.x * 8 + wid;
    const float* __restrict__ row = affine_w + (size_t)j * WDIM;

    float acc[BB];
#pragma unroll
    for (int b = 0; b < BB; b++) acc[b] = 0.f;
#pragma unroll 4
    for (int k = lid; k < WDIM; k += 32) {
        const float rv = row[k];
#pragma unroll
        for (int b = 0; b < BB; b++) acc[b] += rv * sw[b][k];
    }
#pragma unroll
    for (int b = 0; b < BB; b++)
#pragma unroll
        for (int off = 16; off > 0; off >>= 1)
            acc[b] += __shfl_xor_sync(0xFFFFFFFFu, acc[b], off);

    if (lid < BB) {
        const float gain = 1.0f / sqrtf((float)WDIM);
        g_proj[lid * 3 * CIN + j] = acc[lid] * gain + affine_b[j];
    }
}

// ---------------------------------------------------------------------------
// prep kernel 2 (fused): styles = m1*m2+m3, pack weights fp16, wsq, dcoefs
// ---------------------------------------------------------------------------
__global__ void k_prep(const float* __restrict__ weight) {
    const int co = blockIdx.x, ci = threadIdx.x;

    float st[BB];
#pragma unroll
    for (int b = 0; b < BB; b++) {
        const float m1 = g_proj[b * 3 * CIN + 0 * CIN + ci];
        const float m2 = g_proj[b * 3 * CIN + 1 * CIN + ci];
        const float m3 = g_proj[b * 3 * CIN + 2 * CIN + ci];
        st[b] = m1 * m2 + m3;
    }
    if (co == 0) {
#pragma unroll
        for (int b = 0; b < BB; b++) g_styles[b * CIN + ci] = st[b];
    }

    const float* __restrict__ wp = weight + ((size_t)co * CIN + ci) * 9;
    float s = 0.f;
#pragma unroll
    for (int t = 0; t < 9; t++) {
        const float v = wp[t];
        s += v * v;
        g_a[((size_t)t * COUT + co) * CIN + ci] = __float2half(v);
    }
    float p[BB];
#pragma unroll
    for (int b = 0; b < BB; b++) p[b] = st[b] * st[b] * s;
#pragma unroll
    for (int b = 0; b < BB; b++)
#pragma unroll
        for (int off = 16; off > 0; off >>= 1)
            p[b] += __shfl_xor_sync(0xFFFFFFFFu, p[b], off);
    __shared__ float red[BB][17];
    const int wrp = ci >> 5, lane = ci & 31;
    if (lane == 0)
#pragma unroll
        for (int b = 0; b < BB; b++) red[b][wrp] = p[b];
    __syncthreads();
    if (ci < BB) {
        float acc = 0.f;
#pragma unroll
        for (int k = 0; k < 16; k++) acc += red[ci][k];
        g_dcoefs[ci * COUT + co] = rsqrtf(acc + 1e-8f);
    }
}

// ---------------------------------------------------------------------------
// prep kernel 3: pack modulated input (fp16) + padding ring (fused)
// ---------------------------------------------------------------------------
__global__ void k_pack_x(const float* __restrict__ x) {
    const int b = blockIdx.z, hp = blockIdx.y, cin0 = blockIdx.x * 32;
    const int t = threadIdx.x;
    const __half zz = __float2half(0.f);

    if (hp == 0 || hp == 65) {
        for (int idx = t; idx < 66 * 32; idx += 256) {
            const int pw = idx >> 5, c = idx & 31;
            g_x[((size_t)b * NPIX + hp * PADW + pw) * CIN + cin0 + c] = zz;
        }
        return;
    }
    const int h = hp - 1;
    __shared__ float tile[32][65];
    {
        const int w = t & 63, i0 = t >> 6;
#pragma unroll
        for (int j = 0; j < 8; j++) {
            const int ci = i0 * 8 + j;
            tile[ci][w] = x[(((size_t)b * CIN + cin0 + ci) * RES + h) * RES + w];
        }
    }
    if (t < 64) {
        const int c = t & 31, pw = (t < 32) ? 0 : 65;
        g_x[((size_t)b * NPIX + hp * PADW + pw) * CIN + cin0 + c] = zz;
    }
    __syncthreads();
    {
        const int c = t & 31, w0 = t >> 5;
        const float st = g_styles[b * CIN + cin0 + c];
        for (int w = w0; w < 64; w += 8) {
            g_x[((size_t)b * NPIX + hp * PADW + (w + 1)) * CIN + cin0 + c] =
                __float2half(tile[c][w] * st);
        }
    }
}

// ---------------------------------------------------------------------------
// main conv kernel: fp16 implicit GEMM with B-halo reuse across taps
// CTA: M=128 couts x N=128 pixels (2 rows), 256 thr / 8 warps, wtile 64x32
// loop: 8 cin-chunks x 9 taps = 72 iters; A 16KB/iter, B halo 33.8KB/chunk
// ---------------------------------------------------------------------------
#define A_BUF   16384
#define OFF_B0  32768
#define B_BUF   33792                 // 264 rows x 128B
#define SMEM_DYN (OFF_B0 + 2 * B_BUF) // 100352

extern __shared__ __align__(1024) char smem[];

__global__ void __launch_bounds__(256, 2)
k_conv(const float* __restrict__ bias,
       const float* __restrict__ noise_const,
       const float* __restrict__ noise_strength,
       float* __restrict__ out) {
    const int tid   = threadIdx.x;
    const int wid   = tid >> 5;
    const int lid   = tid & 31;
    const int ptile = blockIdx.x;            // 0..31 (2 image rows each)
    const int cout0 = blockIdx.y * 128;      // 0..3
    const int b     = blockIdx.z;
    const int wm    = wid >> 2;              // 0..1 (M warp: 64 rows)
    const int wn    = wid & 3;               // 0..3 (N warp: 32 pixels)

    const uint32_t sb = smem_u32(smem);

    // ---- loader invariants
    const size_t arow = (size_t)(cout0 + (tid & 127)) * CIN;
    // halo: padded rows [2*ptile .. 2*ptile+3] x full 66 cols, contiguous
    const size_t pixbase = (size_t)b * NPIX + (size_t)ptile * 132;

    uint32_t swA[8];
#pragma unroll
    for (int sg = 0; sg < 8; sg++)
        swA[sg] = sw128((uint32_t)((tid & 127) * 128 + sg * 16));

    // ---- ldmatrix per-lane bases
    uint32_t aoff[4];
#pragma unroll
    for (int mt = 0; mt < 4; mt++)
        aoff[mt] = (uint32_t)((wm * 64 + mt * 16 + (lid & 15)) << 7) + ((lid >> 4) << 4);
    // B: lane pixel -> halo row-index base (output pixel at halo (row+0..), tap adds (dh*66+dw))
    uint32_t q0b[2];
#pragma unroll
    for (int p = 0; p < 2; p++) {
        const int plocal = wn * 32 + p * 16 + ((lid >> 4) & 1) * 8 + (lid & 7);
        const int q0 = (plocal >> 6) * 66 + (plocal & 63);
        q0b[p] = (uint32_t)(q0 * 128) + (((lid >> 3) & 1) << 4);
    }

    float acc[4][4][4];
#pragma unroll
    for (int mt = 0; mt < 4; mt++)
#pragma unroll
        for (int nt = 0; nt < 4; nt++)
#pragma unroll
            for (int i = 0; i < 4; i++) acc[mt][nt][i] = 0.f;

    // ---- stage loader: A(it) always; B halo when tap==0
    auto load_stage = [&](int it) {
        const int chunk = it / 9, tap = it - chunk * 9;
        const int cin0 = chunk << 6;
        if (tid < 128) {
            const char* asrc = (const char*)(g_a + ((size_t)tap * COUT * CIN + arow + cin0));
            const uint32_t da = sb + (uint32_t)(it & 1) * A_BUF;
#pragma unroll
            for (int sg = 0; sg < 8; sg++) cpa16(da + swA[sg], asrc + sg * 16);
        }
        if (tap == 0) {
            const uint32_t db = sb + OFF_B0 + (uint32_t)(chunk & 1) * B_BUF;
            {
                const char* bsrc = (const char*)(g_x + ((pixbase + tid) * CIN + cin0));
#pragma unroll
                for (int sg = 0; sg < 8; sg++)
                    cpa16(db + sw128((uint32_t)(tid * 128 + sg * 16)), bsrc + sg * 16);
            }
            if (tid < 8) {
                const int hr = 256 + tid;
                const char* bsrc = (const char*)(g_x + ((pixbase + hr) * CIN + cin0));
#pragma unroll
                for (int sg = 0; sg < 8; sg++)
                    cpa16(db + sw128((uint32_t)(hr * 128 + sg * 16)), bsrc + sg * 16);
            }
        }
        CP_COMMIT();
    };

    load_stage(0);

#pragma unroll 1
    for (int it = 0; it < 72; it++) {
        __syncthreads();                       // compute(it-1) done -> bufs free
        if (it + 1 < 72) { load_stage(it + 1); CP_WAIT1(); }
        else             { CP_WAIT0(); }
        __syncthreads();                       // A(it), B(chunk) visible

        const int chunk = it / 9, tap = it - chunk * 9;
        const uint32_t stgA = sb + (uint32_t)(it & 1) * A_BUF;
        const uint32_t bbase = sb + OFF_B0 + (uint32_t)(chunk & 1) * B_BUF;
        const uint32_t toff = (uint32_t)(((tap / 3) * 66 + (tap % 3)) * 128);

#pragma unroll
        for (int kk = 0; kk < 4; kk++) {
            uint32_t af[4][4], bf[2][4];
#pragma unroll
            for (int mt = 0; mt < 4; mt++)
                ldsm4(af[mt], stgA + sw128(aoff[mt] + kk * 32));
#pragma unroll
            for (int p = 0; p < 2; p++)
                ldsm4(bf[p], bbase + sw128(q0b[p] + toff + kk * 32));
#pragma unroll
            for (int p = 0; p < 2; p++)
#pragma unroll
                for (int h2 = 0; h2 < 2; h2++)
#pragma unroll
                    for (int mt = 0; mt < 4; mt++)
                        mma_f16(acc[mt][p * 2 + h2], af[mt], &bf[p][h2 * 2]);
        }
    }

    // ---- epilogue: demodulate, noise, bias, lrelu*sqrt(2), float2 stores
    const int g = lid >> 2, t2 = (lid & 3) * 2;
    const float ns = noise_strength[0];
    float nz[4][2];
    int hh[4], ww[4];
#pragma unroll
    for (int nt = 0; nt < 4; nt++) {
        const int n = ptile * 128 + wn * 32 + nt * 8 + t2;
        hh[nt] = n >> 6; ww[nt] = n & 63;
        nz[nt][0] = noise_const[hh[nt] * RES + ww[nt]] * ns;
        nz[nt][1] = noise_const[hh[nt] * RES + ww[nt] + 1] * ns;
    }
#pragma unroll
    for (int mt = 0; mt < 4; mt++) {
#pragma unroll
        for (int rr = 0; rr < 2; rr++) {
            const int co = cout0 + wm * 64 + mt * 16 + g + rr * 8;
            const float dc = g_dcoefs[b * COUT + co];
            const float bi = bias[co];
#pragma unroll
            for (int nt = 0; nt < 4; nt++) {
                float v0 = acc[mt][nt][rr * 2 + 0] * dc + nz[nt][0] + bi;
                float v1 = acc[mt][nt][rr * 2 + 1] * dc + nz[nt][1] + bi;
                v0 = (v0 > 0.f ? v0 : 0.2f * v0) * 1.4142135623730951f;
                v1 = (v1 > 0.f ? v1 : 0.2f * v1) * 1.4142135623730951f;
                float2* o = (float2*)&out[(((size_t)b * COUT + co) * RES + hh[nt]) * RES + ww[nt]];
                *o = make_float2(v0, v1);
            }
        }
    }
}

// ---------------------------------------------------------------------------
// launch: 4 kernels (ncu -s 5 lands on k_conv)
// ---------------------------------------------------------------------------
extern "C" void kernel_launch(void* const* d_in, const int* in_sizes, int n_in,
                              void* d_out, int out_size) {
    (void)in_sizes; (void)n_in; (void)out_size;
    const float* x              = (const float*)d_in[0];
    const float* w              = (const float*)d_in[1];
    const float* affine_w       = (const float*)d_in[2];
    const float* affine_b       = (const float*)d_in[3];
    const float* weight         = (const float*)d_in[4];
    const float* bias           = (const float*)d_in[5];
    const float* noise_const    = (const float*)d_in[6];
    const float* noise_strength = (const float*)d_in[7];
    float* out = (float*)d_out;

    cudaFuncSetAttribute(k_conv, cudaFuncAttributeMaxDynamicSharedMemorySize, SMEM_DYN);

    k_styles<<<192, 256>>>(w, affine_w, affine_b);
    k_prep<<<COUT, 512>>>(weight);
    k_pack_x<<<dim3(16, 66, BB), 256>>>(x);

    dim3 grid(32, COUT / 128, BB);
    k_conv<<<grid, 256, SMEM_DYN>>>(bias, noise_const, noise_strength, out);
}